// round 7
// baseline (speedup 1.0000x reference)
#include <cuda_runtime.h>
#include <cuda_bf16.h>
#include <math.h>

#define BATCH 32
#define EPSV 1e-6f
#define SCALV 5.0f

typedef unsigned long long u64;

// ---------------- scratch (static device globals; alloc-free) ----------------
__device__ float g_h1[2*BATCH*64*64*64];
__device__ float g_h2[2*BATCH*64*64*64];
__device__ float g_t1[BATCH*64*64*64];
__device__ float g_parts[2*BATCH*16*64*64];
__device__ float g_norm[BATCH*16*64*64];
__device__ float g_fxs[BATCH*32*64*64];
__device__ float g_enc[BATCH*48*64*64];
__device__ float g_h128[BATCH*32*128*128];
__device__ float g_mu[BATCH*16*2];
__device__ float g_Linv[BATCH*16*4];
__device__ float g_mua[BATCH*16*2];
__device__ float g_Linva[BATCH*16*4];
__device__ float g_alpha[BATCH*16*32];
__device__ float g_partial[1536];
__device__ float2 g_wc2[2*64*16*8];          // parity weights [grp(2)][cin][i(16)][k(8)]

// dup-weight pool (sizes COUT*CIN*10 float2 each)
#define OFF_ESW2 0
#define OFF_ESWP (OFF_ESW2 + 64*64*10)
#define OFF_EAW1 (OFF_ESWP + 16*64*10)
#define OFF_EAW2 (OFF_EAW1 + 64*64*10)
#define OFF_DW1  (OFF_EAW2 + 32*64*10)
#define OFF_DW3  (OFF_DW1  + 64*48*10)
#define DUP_TOTAL (OFF_DW3 + 3*32*10)
__device__ float2 g_dupw[DUP_TOTAL];

// ---------------- f32x2 packed helpers ----------------
__device__ __forceinline__ u64 pk2(float lo, float hi) {
    u64 r; asm("mov.b64 %0, {%1, %2};" : "=l"(r) : "f"(lo), "f"(hi)); return r;
}
__device__ __forceinline__ void upk2(u64 v, float& lo, float& hi) {
    asm("mov.b64 {%0, %1}, %2;" : "=f"(lo), "=f"(hi) : "l"(v));
}
__device__ __forceinline__ void fma2(u64& d, u64 a, u64 b) {
    asm("fma.rn.f32x2 %0, %1, %2, %0;" : "+l"(d) : "l"(a), "l"(b));
}
__device__ __forceinline__ unsigned sptr(const void* p) {
    return (unsigned)__cvta_generic_to_shared(p);
}
__device__ __forceinline__ void lds_v2u64(u64& a, u64& b, unsigned addr) {
    asm volatile("ld.shared.v2.u64 {%0, %1}, [%2];" : "=l"(a), "=l"(b) : "r"(addr));
}
__device__ __forceinline__ u64 lds_u64(unsigned addr) {
    u64 r; asm volatile("ld.shared.b64 %0, [%1];" : "=l"(r) : "r"(addr)); return r;
}

// ---------------- reductions ----------------
__device__ __forceinline__ float warp_sum(float v) {
    #pragma unroll
    for (int o = 16; o; o >>= 1) v += __shfl_xor_sync(0xffffffffu, v, o);
    return v;
}
__device__ __forceinline__ float block_sum256(float v, float* red) {
    int tid = threadIdx.x;
    v = warp_sum(v);
    if ((tid & 31) == 0) red[tid >> 5] = v;
    __syncthreads();
    float r = 0.f;
    if (tid < 8) r = red[tid];
    if (tid < 32) r = warp_sum(r);
    if (tid == 0) red[0] = r;
    __syncthreads();
    float out = red[0];
    __syncthreads();
    return out;
}

// ============ weight duplication precompute ============
// dst chunks: [g][cin/4] of 4*ACC*10 float2; within chunk (cc*ACC+i)*10+k
__global__ void dup_weights_kernel(const float* __restrict__ src, float2* __restrict__ dst,
                                   int COUT, int CIN, int ACCv)
{
    int total = COUT * CIN * 10;
    int idx = blockIdx.x * 256 + threadIdx.x;
    if (idx >= total) return;
    int k = idx % 10;
    int t = idx / 10;
    int cin = t % CIN;
    int oc  = t / CIN;
    int g = oc / ACCv, i = oc % ACCv;
    int c0h = cin >> 2, cc = cin & 3;
    float w = (k < 9) ? src[((size_t)oc * CIN + cin) * 9 + k] : 0.f;
    dst[((size_t)(g * (CIN >> 2) + c0h) * 4 * ACCv + cc * ACCv + i) * 10 + k] = make_float2(w, w);
}

// ============ register-blocked packed conv3x3, stride 1, SAME ============
// 32x32 output tile, 256 threads, 2x2 outputs/thread, ACC=16 channels,
// 4-channel staging. ACT: 0 none, 1 relu, 2 sigmoid
template<int CIN, int COUT, int ACC, int ACT>
__global__ __launch_bounds__(256, 2)
void conv3x3_f2(const float* __restrict__ in,
                const float2* __restrict__ dupw,
                const float* __restrict__ bias,
                float* __restrict__ out, int OH, int OW)
{
    __shared__ float s_in[4][34][36];
    __shared__ __align__(16) float2 s_w[4 * ACC * 10];

    constexpr int GROUPS = COUT / ACC;
    const int b   = blockIdx.z / GROUPS;
    const int grp = blockIdx.z % GROUPS;
    const int oc0 = grp * ACC;
    const int tid = threadIdx.x;
    const int tx = tid & 15, ty = tid >> 4;
    const int oy0 = blockIdx.y * 32, ox0 = blockIdx.x * 32;

    const int sr0 = tid >> 3;
    const int sc0 = tid & 7;

    u64 acc[ACC][2];
    #pragma unroll
    for (int i = 0; i < ACC; i++) {
        float bv = bias[oc0 + i];
        acc[i][0] = pk2(bv, bv);
        acc[i][1] = acc[i][0];
    }

    const unsigned inbase = sptr(&s_in[0][0][0]);
    const unsigned wbase  = sptr(&s_w[0]);
    const float2* wchunk = dupw + (size_t)grp * (CIN >> 2) * (4 * ACC * 10);
    const float* ipbase = in + (size_t)b * CIN * OH * OW;

    for (int c0 = 0; c0 < CIN; c0 += 4) {
        // ---- stage 4 input channels (shift-only indexing) ----
        #pragma unroll
        for (int cc = 0; cc < 4; cc++) {
            const float* ip = ipbase + (size_t)(c0 + cc) * OH * OW;
            float* sdst = &s_in[cc][0][0];
            #pragma unroll
            for (int rp = 0; rp < 2; rp++) {
                int r = sr0 + rp * 32;
                if (rp == 0 || r < 34) {
                    int iy = oy0 - 1 + r;
                    bool rowok = (iy >= 0) && (iy < OH);
                    const float* iprow = ip + iy * OW;
                    float* srow = sdst + r * 36;
                    #pragma unroll
                    for (int j = 0; j < 5; j++) {
                        int c = sc0 + 8 * j;
                        if (j < 4 || c < 34) {
                            int ix = ox0 - 1 + c;
                            float v = 0.f;
                            if (rowok && ix >= 0 && ix < OW) v = iprow[ix];
                            srow[c] = v;
                        }
                    }
                }
            }
        }
        // ---- stage weights: straight copy of pre-duplicated 4-channel chunk ----
        {
            const float2* wsrc = wchunk + (size_t)(c0 >> 2) * (4 * ACC * 10);
            #pragma unroll
            for (int idx = tid; idx < 4 * ACC * 10; idx += 256)
                s_w[idx] = wsrc[idx];
        }
        __syncthreads();

        #pragma unroll
        for (int cc = 0; cc < 4; cc++) {
            u64 pr[4][3];
            #pragma unroll
            for (int r = 0; r < 4; r++) {
                unsigned a = inbase + (unsigned)(cc * 34 * 36 + (2 * ty + r) * 36 + 2 * tx) * 4u;
                u64 A = lds_u64(a);
                u64 B = lds_u64(a + 8);
                float a0, a1, b0, b1;
                upk2(A, a0, a1); upk2(B, b0, b1);
                pr[r][0] = A; pr[r][1] = pk2(a1, b0); pr[r][2] = B;
            }
            #pragma unroll
            for (int i = 0; i < ACC; i++) {
                unsigned wa = wbase + (unsigned)(cc * ACC + i) * 80u;
                u64 w[9];
                lds_v2u64(w[0], w[1], wa);
                lds_v2u64(w[2], w[3], wa + 16);
                lds_v2u64(w[4], w[5], wa + 32);
                lds_v2u64(w[6], w[7], wa + 48);
                w[8] = lds_u64(wa + 64);
                #pragma unroll
                for (int dy = 0; dy < 2; dy++)
                    #pragma unroll
                    for (int ky = 0; ky < 3; ky++)
                        #pragma unroll
                        for (int kx = 0; kx < 3; kx++)
                            fma2(acc[i][dy], pr[dy + ky][kx], w[ky * 3 + kx]);
            }
        }
        __syncthreads();
    }

    const int oy = oy0 + 2 * ty, ox = ox0 + 2 * tx;
    #pragma unroll
    for (int i = 0; i < ACC; i++)
        #pragma unroll
        for (int dy = 0; dy < 2; dy++) {
            float v0, v1;
            upk2(acc[i][dy], v0, v1);
            if (ACT == 1) { v0 = fmaxf(v0, 0.f); v1 = fmaxf(v1, 0.f); }
            else if (ACT == 2) { v0 = 1.f / (1.f + expf(-v0)); v1 = 1.f / (1.f + expf(-v1)); }
            *reinterpret_cast<float2*>(out + (((size_t)b * COUT + oc0 + i) * OH + oy + dy) * OW + ox)
                = make_float2(v0, v1);
        }
}

// ============ dual-input stride-2 conv 3->64 ====
__global__ void conv_s2_dual(const float* __restrict__ inA,
                             const float* __restrict__ inB,
                             const float* __restrict__ wt,
                             const float* __restrict__ bias,
                             float* __restrict__ out)
{
    constexpr int TS = 16, IT = TS * 2 + 2;
    __shared__ float s_in[IT][IT];
    __shared__ float s_w[16 * 9];

    const int b   = blockIdx.z >> 2;
    const int oc0 = (blockIdx.z & 3) * 16;
    const float* in = (b < BATCH) ? inA + (size_t)b * 3 * 128 * 128
                                  : inB + (size_t)(b - BATCH) * 3 * 128 * 128;
    const int tid = threadIdx.x;
    const int tx = tid & 15, ty = tid >> 4;
    const int ox = blockIdx.x * TS + tx;
    const int oy = blockIdx.y * TS + ty;
    const int iy0 = blockIdx.y * TS * 2;
    const int ix0 = blockIdx.x * TS * 2;

    float acc[16];
    #pragma unroll
    for (int i = 0; i < 16; i++) acc[i] = bias[oc0 + i];

    for (int cin = 0; cin < 3; ++cin) {
        const float* ip = in + (size_t)cin * 128 * 128;
        for (int idx = tid; idx < IT * IT; idx += 256) {
            int r = idx / IT, c = idx % IT;
            int iy = iy0 + r, ix = ix0 + c;
            float v = 0.f;
            if (iy < 128 && ix < 128) v = ip[iy * 128 + ix];
            s_in[r][c] = v;
        }
        if (tid < 16 * 9)
            s_w[tid] = wt[((oc0 + tid / 9) * 3 + cin) * 9 + (tid % 9)];
        __syncthreads();

        #pragma unroll
        for (int ky = 0; ky < 3; ky++)
            #pragma unroll
            for (int kx = 0; kx < 3; kx++) {
                float v = s_in[ty * 2 + ky][tx * 2 + kx];
                #pragma unroll
                for (int i = 0; i < 16; i++)
                    acc[i] = fmaf(v, s_w[i * 9 + ky * 3 + kx], acc[i]);
            }
        __syncthreads();
    }

    #pragma unroll
    for (int i = 0; i < 16; i++)
        out[(((size_t)b * 64 + oc0 + i) * 64 + oy) * 64 + ox] = fmaxf(acc[i], 0.f);
}

// ============ parity-combined weights for upsample conv (d_w2) ============
// layout: [grp(2)][cin(64)][i(16)][k(8)]
__global__ void wc_precompute_kernel(const float* __restrict__ w2, float2* __restrict__ wc2)
{
    int t = blockIdx.x * 256 + threadIdx.x;
    if (t >= 32 * 64) return;
    int oc = t / 64, cin = t % 64;
    int grp = oc >> 4, i = oc & 15;
    float w[3][3];
    #pragma unroll
    for (int r = 0; r < 3; r++)
        #pragma unroll
        for (int c = 0; c < 3; c++)
            w[r][c] = w2[t * 9 + r * 3 + c];
    float ry[2][2][3];
    #pragma unroll
    for (int c = 0; c < 3; c++) {
        ry[0][0][c] = w[0][c];
        ry[0][1][c] = w[1][c] + w[2][c];
        ry[1][0][c] = w[0][c] + w[1][c];
        ry[1][1][c] = w[2][c];
    }
    float2* dst = wc2 + ((size_t)(grp * 64 + cin) * 16 + i) * 8;
    #pragma unroll
    for (int py = 0; py < 2; py++)
        #pragma unroll
        for (int dr = 0; dr < 2; dr++)
            #pragma unroll
            for (int dc = 0; dc < 2; dc++) {
                float v_px0 = (dc == 0) ? ry[py][dr][0] : (ry[py][dr][1] + ry[py][dr][2]);
                float v_px1 = (dc == 0) ? (ry[py][dr][0] + ry[py][dr][1]) : ry[py][dr][2];
                dst[py * 4 + dr * 2 + dc] = make_float2(v_px0, v_px1);
            }
}

// ============ parity conv: t1[64,64x64] -> relu -> h128[32,128x128] ============
__global__ __launch_bounds__(256, 2)
void parity_conv_kernel(const float* __restrict__ in,
                        const float2* __restrict__ wc2,
                        const float* __restrict__ bias,
                        float* __restrict__ out)
{
    __shared__ float s_in[18][20];
    __shared__ __align__(16) float2 s_w[128];

    const int b   = blockIdx.z >> 1;
    const int grp = blockIdx.z & 1;
    const int oc0 = grp * 16;
    const int tid = threadIdx.x;
    const int tx = tid & 15, ty = tid >> 4;
    const int i0 = blockIdx.y * 16, j0 = blockIdx.x * 16;

    const int sr0 = tid >> 4;
    const int scp = tid & 15;

    u64 acc[16][2];
    #pragma unroll
    for (int i = 0; i < 16; i++) {
        float bv = bias[oc0 + i];
        acc[i][0] = pk2(bv, bv);
        acc[i][1] = acc[i][0];
    }
    const unsigned wbase = sptr(&s_w[0]);
    const float* ipbase = in + (size_t)b * 64 * 4096;
    const float2* wgrp = wc2 + (size_t)grp * 64 * 128;

    for (int cin = 0; cin < 64; ++cin) {
        const float* ip = ipbase + (size_t)cin * 4096;
        #pragma unroll
        for (int rp = 0; rp < 2; rp++) {
            int r = sr0 + rp * 16;
            if (rp == 0 || r < 18) {
                int iy = i0 - 1 + r;
                bool rowok = (iy >= 0) && (iy < 64);
                const float* iprow = ip + iy * 64;
                float* srow = &s_in[r][0];
                #pragma unroll
                for (int j = 0; j < 2; j++) {
                    int c = scp + 16 * j;
                    if (j == 0 || c < 18) {
                        int ix = j0 - 1 + c;
                        float v = 0.f;
                        if (rowok && ix >= 0 && ix < 64) v = iprow[ix];
                        srow[c] = v;
                    }
                }
            }
        }
        if (tid < 128) s_w[tid] = wgrp[(size_t)cin * 128 + tid];
        __syncthreads();

        float p[3][3];
        #pragma unroll
        for (int r = 0; r < 3; r++)
            #pragma unroll
            for (int c = 0; c < 3; c++)
                p[r][c] = s_in[ty + r][tx + c];
        u64 q[3][2];
        #pragma unroll
        for (int r = 0; r < 3; r++) {
            q[r][0] = pk2(p[r][0], p[r][1]);
            q[r][1] = pk2(p[r][1], p[r][2]);
        }

        #pragma unroll
        for (int i = 0; i < 16; i++) {
            unsigned wa = wbase + i * 64u;
            u64 w[8];
            lds_v2u64(w[0], w[1], wa);
            lds_v2u64(w[2], w[3], wa + 16);
            lds_v2u64(w[4], w[5], wa + 32);
            lds_v2u64(w[6], w[7], wa + 48);
            #pragma unroll
            for (int py = 0; py < 2; py++)
                #pragma unroll
                for (int dr = 0; dr < 2; dr++)
                    #pragma unroll
                    for (int dc = 0; dc < 2; dc++)
                        fma2(acc[i][py], q[py + dr][dc], w[py * 4 + dr * 2 + dc]);
        }
        __syncthreads();
    }

    const int oy2 = 2 * (i0 + ty), ox2 = 2 * (j0 + tx);
    #pragma unroll
    for (int i = 0; i < 16; i++)
        #pragma unroll
        for (int py = 0; py < 2; py++) {
            float v0, v1;
            upk2(acc[i][py], v0, v1);
            v0 = fmaxf(v0, 0.f); v1 = fmaxf(v1, 0.f);
            *reinterpret_cast<float2*>(out + (((size_t)b * 32 + oc0 + i) * 128 + oy2 + py) * 128 + ox2)
                = make_float2(v0, v1);
        }
}

// ------- fused spatial softmax + soft-argmax moments (both streams) -------
__global__ void softmax_mu_kernel(float* __restrict__ p,
                                  float* __restrict__ mu, float* __restrict__ Li,
                                  float* __restrict__ mua, float* __restrict__ Lia)
{
    float* base = p + (size_t)blockIdx.x * 4096;
    __shared__ float red[256];
    int tid = threadIdx.x;
    float m = -1e30f;
    float vals[16];
    #pragma unroll
    for (int j = 0; j < 16; j++) { vals[j] = base[tid + j * 256]; m = fmaxf(m, vals[j]); }
    red[tid] = m; __syncthreads();
    for (int s = 128; s > 0; s >>= 1) { if (tid < s) red[tid] = fmaxf(red[tid], red[tid + s]); __syncthreads(); }
    m = red[0]; __syncthreads();
    float sum = 0.f;
    #pragma unroll
    for (int j = 0; j < 16; j++) { vals[j] = expf(vals[j] - m); sum += vals[j]; }
    float tot = block_sum256(sum, red);
    float inv = 1.f / tot;
    float s0=0,s1=0,s2=0,s3=0,s4=0;
    #pragma unroll
    for (int j = 0; j < 16; j++) {
        int i = tid + j * 256;
        float pv = vals[j] * inv;
        base[i] = pv;
        int h = i >> 6, w = i & 63;
        float gy = -1.f + 2.f * h / 63.f;
        float gx = -1.f + 2.f * w / 63.f;
        s0 += pv * gy; s1 += pv * gx;
        s2 += pv * gy * gy; s3 += pv * gy * gx; s4 += pv * gx * gx;
    }
    s0 = block_sum256(s0, red);
    s1 = block_sum256(s1, red);
    s2 = block_sum256(s2, red);
    s3 = block_sum256(s3, red);
    s4 = block_sum256(s4, red);
    if (tid == 0) {
        float muy = s0, mux = s1;
        float c00 = s2 - muy * muy, c01 = s3 - muy * mux, c11 = s4 - mux * mux;
        float a  = sqrtf(c00 + EPSV);
        float bb = c01 / (a + EPSV);
        float c  = sqrtf(fmaxf(c11 - bb * bb, 0.f) + EPSV);
        float det = a * c;
        float sc = SCALV / (det + EPSV);
        int bk = blockIdx.x;
        float* pmu = (bk < 512) ? mu : mua;
        float* pLi = (bk < 512) ? Li : Lia;
        int o = bk & 511;
        pmu[o * 2 + 0] = muy; pmu[o * 2 + 1] = mux;
        pLi[o * 4 + 0] = sc * c;     pLi[o * 4 + 1] = 0.f;
        pLi[o * 4 + 2] = sc * (-bb); pLi[o * 4 + 3] = sc * a;
    }
}

// ---------------- alpha = einsum('bfhw,bkhw->bkf') ----------------
__global__ void alpha_kernel(const float* __restrict__ fxs,
                             const float* __restrict__ parts,
                             float* __restrict__ alpha)
{
    int bk = blockIdx.x;
    int b = bk >> 4;
    __shared__ float sp[4096];
    __shared__ float red[256];
    int tid = threadIdx.x;
    const float* pb = parts + (size_t)bk * 4096;
    for (int i = tid; i < 4096; i += 256) sp[i] = pb[i];
    __syncthreads();
    for (int f = 0; f < 32; f++) {
        const float* fb = fxs + ((size_t)b * 32 + f) * 4096;
        float s = 0.f;
        for (int i = tid; i < 4096; i += 256) s += fb[i] * sp[i];
        s = block_sum256(s, red);
        if (tid == 0) alpha[(size_t)bk * 32 + f] = s;
    }
}

// ---------------- Cauchy heat render + normalization ----------------
__global__ void heat_kernel(const float* __restrict__ mu, const float* __restrict__ Linv,
                            float* __restrict__ enc, float* __restrict__ norm)
{
    int bk = blockIdx.x;
    int b = bk >> 4, k = bk & 15;
    float muy = mu[bk*2], mux = mu[bk*2+1];
    float L00 = Linv[bk*4], L01 = Linv[bk*4+1], L10 = Linv[bk*4+2], L11 = Linv[bk*4+3];
    int tid = threadIdx.x;
    __shared__ float red[256];
    float hv[16]; float sum = 0.f;
    #pragma unroll
    for (int j = 0; j < 16; j++) {
        int i = tid + j * 256;
        int h = i >> 6, w = i & 63;
        float dy = (-1.f + 2.f * h / 63.f) - muy;
        float dx = (-1.f + 2.f * w / 63.f) - mux;
        float p0 = dy * L00 + dx * L10;
        float p1 = dy * L01 + dx * L11;
        float he = 1.f / (1.f + p0 * p0 + p1 * p1);
        hv[j] = he; sum += he;
    }
    float tot = block_sum256(sum, red);
    float inv = 1.f / (tot + EPSV);
    float* eb = enc + (((size_t)b * 48 + k) * 4096);
    float* nb = norm + (size_t)bk * 4096;
    #pragma unroll
    for (int j = 0; j < 16; j++) {
        int i = tid + j * 256;
        eb[i] = hv[j];
        nb[i] = hv[j] * inv;
    }
}

// ---------------- fmap = einsum('bkf,bkhw->bfhw') -> enc ch [16,48) ----------
__global__ void fmap_kernel(const float* __restrict__ alpha,
                            const float* __restrict__ norm,
                            float* __restrict__ enc)
{
    int b = blockIdx.y;
    int pix = blockIdx.x * 256 + threadIdx.x;
    __shared__ float sal[512];
    for (int i = threadIdx.x; i < 512; i += 256) sal[i] = alpha[(size_t)b * 512 + i];
    __syncthreads();
    float nv[16];
    #pragma unroll
    for (int k = 0; k < 16; k++) nv[k] = norm[((size_t)b * 16 + k) * 4096 + pix];
    #pragma unroll
    for (int f = 0; f < 32; f++) {
        float s = 0.f;
        #pragma unroll
        for (int k = 0; k < 16; k++) s = fmaf(sal[k * 32 + f], nv[k], s);
        enc[((size_t)b * 48 + 16 + f) * 4096 + pix] = s;
    }
}

// ---------------- losses ----------------
__global__ void rec_loss_partial_kernel(const float* __restrict__ x,
                                        const float* __restrict__ rec,
                                        float* __restrict__ partial)
{
    __shared__ float red[256];
    int i0 = blockIdx.x * 1024 + threadIdx.x;
    float s = 0.f;
    #pragma unroll
    for (int j = 0; j < 4; j++) {
        int i = i0 + j * 256;
        float d = x[i] - rec[i];
        s += d * d;
    }
    s = block_sum256(s, red);
    if (threadIdx.x == 0) partial[blockIdx.x] = s;
}

__global__ void final_loss_kernel(const float* __restrict__ partial,
                                  const float* __restrict__ mu, const float* __restrict__ Li,
                                  const float* __restrict__ mua, const float* __restrict__ Lia,
                                  const float* __restrict__ coord, const float* __restrict__ vec,
                                  float* __restrict__ out, int out_size)
{
    __shared__ float red[256];
    int tid = threadIdx.x;
    float s0=0,s1=0,s2=0,s3=0;
    for (int i = tid; i < 1536; i += 256) s0 += partial[i];
    for (int i = tid; i < 1024; i += 256) { float d = mu[i] - mua[i]; s1 += d * d; }
    for (int i = tid; i < 2048; i += 256) { float d = Li[i] - Lia[i]; s2 += d * d; }
    for (int i = tid; i < 1024; i += 256) { float d = mua[i] - (coord[i] + vec[i]); s3 += d * d; }
    s0 = block_sum256(s0, red);
    s1 = block_sum256(s1, red);
    s2 = block_sum256(s2, red);
    s3 = block_sum256(s3, red);
    if (tid == 0) {
        float loss = s0 / 1572864.f + s1 / 1024.f + 0.01f * (s2 / 2048.f) + s3 / 1024.f;
        if (out_size > 1572864) out[1572864] = loss;
    }
}

// ---------------- launch ----------------
extern "C" void kernel_launch(void* const* d_in, const int* in_sizes, int n_in,
                              void* d_out, int out_size)
{
    const float* x     = (const float*)d_in[0];
    const float* xsp   = (const float*)d_in[1];
    const float* xapp  = (const float*)d_in[2];
    const float* coord = (const float*)d_in[3];
    const float* vec   = (const float*)d_in[4];
    const float* es_w1 = (const float*)d_in[5];
    const float* es_b1 = (const float*)d_in[6];
    const float* es_w2 = (const float*)d_in[7];
    const float* es_b2 = (const float*)d_in[8];
    const float* es_wp = (const float*)d_in[9];
    const float* es_bp = (const float*)d_in[10];
    const float* ea_w1 = (const float*)d_in[11];
    const float* ea_b1 = (const float*)d_in[12];
    const float* ea_w2 = (const float*)d_in[13];
    const float* ea_b2 = (const float*)d_in[14];
    const float* d_w1  = (const float*)d_in[15];
    const float* d_b1  = (const float*)d_in[16];
    const float* d_w2  = (const float*)d_in[17];
    const float* d_b2  = (const float*)d_in[18];
    const float* d_w3  = (const float*)d_in[19];
    const float* d_b3  = (const float*)d_in[20];
    float* out = (float*)d_out;

    float *h1,*h2,*t1,*parts,*normb,*fxs,*enc,*h128,*mu,*Li,*mua,*Lia,*al,*part;
    float2 *wc2, *dupw;
    cudaGetSymbolAddress((void**)&h1, g_h1);
    cudaGetSymbolAddress((void**)&h2, g_h2);
    cudaGetSymbolAddress((void**)&t1, g_t1);
    cudaGetSymbolAddress((void**)&parts, g_parts);
    cudaGetSymbolAddress((void**)&normb, g_norm);
    cudaGetSymbolAddress((void**)&fxs, g_fxs);
    cudaGetSymbolAddress((void**)&enc, g_enc);
    cudaGetSymbolAddress((void**)&h128, g_h128);
    cudaGetSymbolAddress((void**)&mu, g_mu);
    cudaGetSymbolAddress((void**)&Li, g_Linv);
    cudaGetSymbolAddress((void**)&mua, g_mua);
    cudaGetSymbolAddress((void**)&Lia, g_Linva);
    cudaGetSymbolAddress((void**)&al, g_alpha);
    cudaGetSymbolAddress((void**)&part, g_partial);
    cudaGetSymbolAddress((void**)&wc2, g_wc2);
    cudaGetSymbolAddress((void**)&dupw, g_dupw);

    const size_t IMG64 = (size_t)64 * 4096;
    const size_t PIMG  = (size_t)16 * 4096;

    dim3 blk(256);

    // ---- weight precomputes (tiny) ----
    wc_precompute_kernel<<<8, blk>>>(d_w2, wc2);
    dup_weights_kernel<<<(64*64*10+255)/256, blk>>>(es_w2, dupw + OFF_ESW2, 64, 64, 16);
    dup_weights_kernel<<<(16*64*10+255)/256, blk>>>(es_wp, dupw + OFF_ESWP, 16, 64, 16);
    dup_weights_kernel<<<(64*64*10+255)/256, blk>>>(ea_w1, dupw + OFF_EAW1, 64, 64, 16);
    dup_weights_kernel<<<(32*64*10+255)/256, blk>>>(ea_w2, dupw + OFF_EAW2, 32, 64, 16);
    dup_weights_kernel<<<(64*48*10+255)/256, blk>>>(d_w1,  dupw + OFF_DW1,  64, 48, 16);
    dup_weights_kernel<<<(3*32*10+255)/256,  blk>>>(d_w3,  dupw + OFF_DW3,   3, 32, 3);

    // ---- merged encoder (batch 64: 0..31 shape/xapp, 32..63 appearance/xsp) ----
    conv_s2_dual<<<dim3(4, 4, 256), blk>>>(xapp, xsp, es_w1, es_b1, h1);
    conv3x3_f2<64,64,16,1><<<dim3(2, 2, 256), blk>>>(h1, dupw + OFF_ESW2, es_b2, h2, 64, 64);
    conv3x3_f2<64,16,16,0><<<dim3(2, 2, 64),  blk>>>(h2, dupw + OFF_ESWP, es_bp, parts, 64, 64);
    softmax_mu_kernel<<<1024, blk>>>(parts, mu, Li, mua, Lia);

    // ---- appearance-only tail ----
    conv3x3_f2<64,64,16,1><<<dim3(2, 2, 128), blk>>>(h2 + BATCH * IMG64, dupw + OFF_EAW1, ea_b1, t1, 64, 64);
    conv3x3_f2<64,32,16,0><<<dim3(2, 2, 64),  blk>>>(t1, dupw + OFF_EAW2, ea_b2, fxs, 64, 64);
    alpha_kernel<<<512, blk>>>(fxs, parts + BATCH * PIMG, al);

    // ---- encoding ----
    heat_kernel<<<512, blk>>>(mu, Li, enc, normb);
    fmap_kernel<<<dim3(16, BATCH), blk>>>(al, normb, enc);

    // ---- decoder ----
    conv3x3_f2<48,64,16,1><<<dim3(2, 2, 128), blk>>>(enc, dupw + OFF_DW1, d_b1, t1, 64, 64);
    parity_conv_kernel<<<dim3(4, 4, 64), blk>>>(t1, wc2, d_b2, h128);
    conv3x3_f2<32,3,3,2><<<dim3(4, 4, 32), blk>>>(h128, dupw + OFF_DW3, d_b3, out, 128, 128);

    // ---- loss ----
    rec_loss_partial_kernel<<<1536, blk>>>(x, out, part);
    final_loss_kernel<<<1, blk>>>(part, mu, Li, mua, Lia, coord, vec, out, out_size);
}

// round 10
// speedup vs baseline: 1.3346x; 1.3346x over previous
#include <cuda_runtime.h>
#include <cuda_bf16.h>
#include <math.h>

#define BATCH 32
#define EPSV 1e-6f
#define SCALV 5.0f

typedef unsigned long long u64;

// ---------------- scratch (static device globals; alloc-free) ----------------
__device__ float g_h1[2*BATCH*64*64*64];
__device__ float g_h2[2*BATCH*64*64*64];
__device__ float g_t1[BATCH*64*64*64];
__device__ float g_parts[2*BATCH*16*64*64];
__device__ float g_norm[BATCH*16*64*64];
__device__ float g_fxs[BATCH*32*64*64];
__device__ float g_enc[BATCH*48*64*64];
__device__ float g_h128[BATCH*32*128*128];
__device__ float g_mu[BATCH*16*2];
__device__ float g_Linv[BATCH*16*4];
__device__ float g_mua[BATCH*16*2];
__device__ float g_Linva[BATCH*16*4];
__device__ float g_alpha[BATCH*16*32];
__device__ float g_partial[1536];
__device__ float2 g_wc2[2*64*16*8];          // parity weights [grp(2)][cin][i(16)][k(8)]

// dup-weight pool (sizes COUT*CIN*10 float2 each), 2-channel chunks
#define OFF_ESW2 0
#define OFF_ESWP (OFF_ESW2 + 64*64*10)
#define OFF_EAW1 (OFF_ESWP + 16*64*10)
#define OFF_EAW2 (OFF_EAW1 + 64*64*10)
#define OFF_DW1  (OFF_EAW2 + 32*64*10)
#define OFF_DW3  (OFF_DW1  + 64*48*10)
#define DUP_TOTAL (OFF_DW3 + 3*32*10)
__device__ float2 g_dupw[DUP_TOTAL];

// ---------------- f32x2 packed helpers ----------------
__device__ __forceinline__ u64 pk2(float lo, float hi) {
    u64 r; asm("mov.b64 %0, {%1, %2};" : "=l"(r) : "f"(lo), "f"(hi)); return r;
}
__device__ __forceinline__ void upk2(u64 v, float& lo, float& hi) {
    asm("mov.b64 {%0, %1}, %2;" : "=f"(lo), "=f"(hi) : "l"(v));
}
__device__ __forceinline__ void fma2(u64& d, u64 a, u64 b) {
    asm("fma.rn.f32x2 %0, %1, %2, %0;" : "+l"(d) : "l"(a), "l"(b));
}
__device__ __forceinline__ unsigned sptr(const void* p) {
    return (unsigned)__cvta_generic_to_shared(p);
}
__device__ __forceinline__ void lds_v2u64(u64& a, u64& b, unsigned addr) {
    asm volatile("ld.shared.v2.u64 {%0, %1}, [%2];" : "=l"(a), "=l"(b) : "r"(addr));
}
__device__ __forceinline__ u64 lds_u64(unsigned addr) {
    u64 r; asm volatile("ld.shared.b64 %0, [%1];" : "=l"(r) : "r"(addr)); return r;
}

// ---------------- cp.async helpers ----------------
__device__ __forceinline__ void cp_async4(unsigned saddr, const void* gaddr, bool ok) {
    asm volatile("cp.async.ca.shared.global [%0], [%1], 4, %2;"
                 :: "r"(saddr), "l"(gaddr), "r"(ok ? 4 : 0));
}
__device__ __forceinline__ void cp_async16(unsigned saddr, const void* gaddr) {
    asm volatile("cp.async.cg.shared.global [%0], [%1], 16;" :: "r"(saddr), "l"(gaddr));
}
__device__ __forceinline__ void cp_commit() {
    asm volatile("cp.async.commit_group;");
}
__device__ __forceinline__ void cp_wait1() {
    asm volatile("cp.async.wait_group 1;");
}

// ---------------- reductions ----------------
__device__ __forceinline__ float warp_sum(float v) {
    #pragma unroll
    for (int o = 16; o; o >>= 1) v += __shfl_xor_sync(0xffffffffu, v, o);
    return v;
}
__device__ __forceinline__ float block_sum256(float v, float* red) {
    int tid = threadIdx.x;
    v = warp_sum(v);
    if ((tid & 31) == 0) red[tid >> 5] = v;
    __syncthreads();
    float r = 0.f;
    if (tid < 8) r = red[tid];
    if (tid < 32) r = warp_sum(r);
    if (tid == 0) red[0] = r;
    __syncthreads();
    float out = red[0];
    __syncthreads();
    return out;
}

// ============ weight duplication precompute (2-channel chunks) ============
// dst chunks: [g][cin/2] of 2*ACC*10 float2; within chunk (cc*ACC+i)*10+k
__global__ void dup_weights_kernel(const float* __restrict__ src, float2* __restrict__ dst,
                                   int COUT, int CIN, int ACCv)
{
    int total = COUT * CIN * 10;
    int idx = blockIdx.x * 256 + threadIdx.x;
    if (idx >= total) return;
    int k = idx % 10;
    int t = idx / 10;
    int cin = t % CIN;
    int oc  = t / CIN;
    int g = oc / ACCv, i = oc % ACCv;
    int c0h = cin >> 1, cc = cin & 1;
    float w = (k < 9) ? src[((size_t)oc * CIN + cin) * 9 + k] : 0.f;
    dst[((size_t)(g * (CIN >> 1) + c0h) * 2 * ACCv + cc * ACCv + i) * 10 + k] = make_float2(w, w);
}

// ============ pipelined register-blocked packed conv3x3, stride 1, SAME =====
// 32x32 output tile, 256 threads, 2x2 outputs/thread, ACC=16 channels,
// cp.async double-buffered 2-channel staging. ACT: 0 none, 1 relu, 2 sigmoid
template<int CIN, int COUT, int ACC, int ACT>
__global__ __launch_bounds__(256, 2)
void conv3x3_f2(const float* __restrict__ in,
                const float2* __restrict__ dupw,
                const float* __restrict__ bias,
                float* __restrict__ out, int OH, int OW)
{
    __shared__ float s_in[2][2][34][36];                  // [buf][cc][r][c]
    __shared__ __align__(16) float2 s_w[2][2 * ACC * 10]; // [buf][...]

    constexpr int GROUPS = COUT / ACC;
    constexpr int NS = CIN / 2;
    const int b   = blockIdx.z / GROUPS;
    const int grp = blockIdx.z % GROUPS;
    const int oc0 = grp * ACC;
    const int tid = threadIdx.x;
    const int tx = tid & 15, ty = tid >> 4;
    const int oy0 = blockIdx.y * 32, ox0 = blockIdx.x * 32;

    const int sr0 = tid >> 3;        // staging row 0..31 (+32 pass 1)
    const int sc0 = tid & 7;         // staging col base

    u64 acc[ACC][2];
    #pragma unroll
    for (int i = 0; i < ACC; i++) {
        float bv = bias[oc0 + i];
        acc[i][0] = pk2(bv, bv);
        acc[i][1] = acc[i][0];
    }

    const unsigned inbase = sptr(&s_in[0][0][0][0]);
    const unsigned wbase  = sptr(&s_w[0][0]);
    const float2* wchunk = dupw + (size_t)grp * (CIN >> 1) * (2 * ACC * 10);
    const float* ipbase = in + (size_t)b * CIN * OH * OW;

    // ---- async stage issue: 2 input channels + weight chunk into buffer `buf`
    auto issue_stage = [&](int c0, int buf) {
        #pragma unroll
        for (int cc = 0; cc < 2; cc++) {
            const float* ip = ipbase + (size_t)(c0 + cc) * OH * OW;
            unsigned sb = inbase + (unsigned)((buf * 2 + cc) * 34 * 36) * 4u;
            #pragma unroll
            for (int rp = 0; rp < 2; rp++) {
                int r = sr0 + rp * 32;
                if (rp == 0 || r < 34) {
                    int iy = oy0 - 1 + r;
                    bool rowok = (iy >= 0) && (iy < OH);
                    const float* iprow = ip + iy * OW;
                    unsigned srow = sb + (unsigned)(r * 36) * 4u;
                    #pragma unroll
                    for (int j = 0; j < 5; j++) {
                        int c = sc0 + 8 * j;
                        if (j < 4 || c < 34) {
                            int ix = ox0 - 1 + c;
                            bool ok = rowok && (ix >= 0) && (ix < OW);
                            const float* ga = ok ? (iprow + ix) : ip;
                            cp_async4(srow + (unsigned)c * 4u, ga, ok);
                        }
                    }
                }
            }
        }
        // weights: 2*ACC*10 float2 = 2560B = 160 x 16B chunks
        if (tid < ACC * 10) {
            const float2* wsrc = wchunk + (size_t)(c0 >> 1) * (2 * ACC * 10);
            cp_async16(wbase + (unsigned)(buf * 2 * ACC * 10 + tid * 2) * 8u,
                       wsrc + tid * 2);
        }
    };

    issue_stage(0, 0);
    cp_commit();

    for (int s = 0; s < NS; s++) {
        const int buf = s & 1;
        if (s + 1 < NS) issue_stage(2 * (s + 1), (s + 1) & 1);
        cp_commit();
        cp_wait1();
        __syncthreads();

        #pragma unroll
        for (int cc = 0; cc < 2; cc++) {
            u64 pr[4][3];
            #pragma unroll
            for (int r = 0; r < 4; r++) {
                unsigned a = inbase + (unsigned)((buf * 2 + cc) * 34 * 36 + (2 * ty + r) * 36 + 2 * tx) * 4u;
                u64 A = lds_u64(a);
                u64 B = lds_u64(a + 8);
                float a0, a1, b0, b1;
                upk2(A, a0, a1); upk2(B, b0, b1);
                pr[r][0] = A; pr[r][1] = pk2(a1, b0); pr[r][2] = B;
            }
            #pragma unroll
            for (int i = 0; i < ACC; i++) {
                unsigned wa = wbase + (unsigned)(buf * 2 * ACC * 10) * 8u
                            + (unsigned)(cc * ACC + i) * 80u;
                u64 w[9];
                lds_v2u64(w[0], w[1], wa);
                lds_v2u64(w[2], w[3], wa + 16);
                lds_v2u64(w[4], w[5], wa + 32);
                lds_v2u64(w[6], w[7], wa + 48);
                w[8] = lds_u64(wa + 64);
                #pragma unroll
                for (int dy = 0; dy < 2; dy++)
                    #pragma unroll
                    for (int ky = 0; ky < 3; ky++)
                        #pragma unroll
                        for (int kx = 0; kx < 3; kx++)
                            fma2(acc[i][dy], pr[dy + ky][kx], w[ky * 3 + kx]);
            }
        }
        __syncthreads();
    }

    const int oy = oy0 + 2 * ty, ox = ox0 + 2 * tx;
    #pragma unroll
    for (int i = 0; i < ACC; i++)
        #pragma unroll
        for (int dy = 0; dy < 2; dy++) {
            float v0, v1;
            upk2(acc[i][dy], v0, v1);
            if (ACT == 1) { v0 = fmaxf(v0, 0.f); v1 = fmaxf(v1, 0.f); }
            else if (ACT == 2) { v0 = 1.f / (1.f + expf(-v0)); v1 = 1.f / (1.f + expf(-v1)); }
            *reinterpret_cast<float2*>(out + (((size_t)b * COUT + oc0 + i) * OH + oy + dy) * OW + ox)
                = make_float2(v0, v1);
        }
}

// ============ dual-input stride-2 conv 3->64 ====
__global__ void conv_s2_dual(const float* __restrict__ inA,
                             const float* __restrict__ inB,
                             const float* __restrict__ wt,
                             const float* __restrict__ bias,
                             float* __restrict__ out)
{
    constexpr int TS = 16, IT = TS * 2 + 2;
    __shared__ float s_in[IT][IT];
    __shared__ float s_w[16 * 9];

    const int b   = blockIdx.z >> 2;
    const int oc0 = (blockIdx.z & 3) * 16;
    const float* in = (b < BATCH) ? inA + (size_t)b * 3 * 128 * 128
                                  : inB + (size_t)(b - BATCH) * 3 * 128 * 128;
    const int tid = threadIdx.x;
    const int tx = tid & 15, ty = tid >> 4;
    const int ox = blockIdx.x * TS + tx;
    const int oy = blockIdx.y * TS + ty;
    const int iy0 = blockIdx.y * TS * 2;
    const int ix0 = blockIdx.x * TS * 2;

    float acc[16];
    #pragma unroll
    for (int i = 0; i < 16; i++) acc[i] = bias[oc0 + i];

    for (int cin = 0; cin < 3; ++cin) {
        const float* ip = in + (size_t)cin * 128 * 128;
        for (int idx = tid; idx < IT * IT; idx += 256) {
            int r = idx / IT, c = idx % IT;
            int iy = iy0 + r, ix = ix0 + c;
            float v = 0.f;
            if (iy < 128 && ix < 128) v = ip[iy * 128 + ix];
            s_in[r][c] = v;
        }
        if (tid < 16 * 9)
            s_w[tid] = wt[((oc0 + tid / 9) * 3 + cin) * 9 + (tid % 9)];
        __syncthreads();

        #pragma unroll
        for (int ky = 0; ky < 3; ky++)
            #pragma unroll
            for (int kx = 0; kx < 3; kx++) {
                float v = s_in[ty * 2 + ky][tx * 2 + kx];
                #pragma unroll
                for (int i = 0; i < 16; i++)
                    acc[i] = fmaf(v, s_w[i * 9 + ky * 3 + kx], acc[i]);
            }
        __syncthreads();
    }

    #pragma unroll
    for (int i = 0; i < 16; i++)
        out[(((size_t)b * 64 + oc0 + i) * 64 + oy) * 64 + ox] = fmaxf(acc[i], 0.f);
}

// ============ parity-combined weights for upsample conv (d_w2) ============
// layout: [grp(2)][cin(64)][i(16)][k(8)]
__global__ void wc_precompute_kernel(const float* __restrict__ w2, float2* __restrict__ wc2)
{
    int t = blockIdx.x * 256 + threadIdx.x;
    if (t >= 32 * 64) return;
    int oc = t / 64, cin = t % 64;
    int grp = oc >> 4, i = oc & 15;
    float w[3][3];
    #pragma unroll
    for (int r = 0; r < 3; r++)
        #pragma unroll
        for (int c = 0; c < 3; c++)
            w[r][c] = w2[t * 9 + r * 3 + c];
    float ry[2][2][3];
    #pragma unroll
    for (int c = 0; c < 3; c++) {
        ry[0][0][c] = w[0][c];
        ry[0][1][c] = w[1][c] + w[2][c];
        ry[1][0][c] = w[0][c] + w[1][c];
        ry[1][1][c] = w[2][c];
    }
    float2* dst = wc2 + ((size_t)(grp * 64 + cin) * 16 + i) * 8;
    #pragma unroll
    for (int py = 0; py < 2; py++)
        #pragma unroll
        for (int dr = 0; dr < 2; dr++)
            #pragma unroll
            for (int dc = 0; dc < 2; dc++) {
                float v_px0 = (dc == 0) ? ry[py][dr][0] : (ry[py][dr][1] + ry[py][dr][2]);
                float v_px1 = (dc == 0) ? (ry[py][dr][0] + ry[py][dr][1]) : ry[py][dr][2];
                dst[py * 4 + dr * 2 + dc] = make_float2(v_px0, v_px1);
            }
}

// ============ pipelined parity conv: t1[64,64x64] -> relu -> h128 ============
__global__ __launch_bounds__(256, 2)
void parity_conv_kernel(const float* __restrict__ in,
                        const float2* __restrict__ wc2,
                        const float* __restrict__ bias,
                        float* __restrict__ out)
{
    __shared__ float s_in[2][18][20];
    __shared__ __align__(16) float2 s_w[2][128];

    const int b   = blockIdx.z >> 1;
    const int grp = blockIdx.z & 1;
    const int oc0 = grp * 16;
    const int tid = threadIdx.x;
    const int tx = tid & 15, ty = tid >> 4;
    const int i0 = blockIdx.y * 16, j0 = blockIdx.x * 16;

    const int sr0 = tid >> 4;
    const int scp = tid & 15;

    u64 acc[16][2];
    #pragma unroll
    for (int i = 0; i < 16; i++) {
        float bv = bias[oc0 + i];
        acc[i][0] = pk2(bv, bv);
        acc[i][1] = acc[i][0];
    }
    const unsigned inbase = sptr(&s_in[0][0][0]);
    const unsigned wbase = sptr(&s_w[0][0]);
    const float* ipbase = in + (size_t)b * 64 * 4096;
    const float2* wgrp = wc2 + (size_t)grp * 64 * 128;

    auto issue_stage = [&](int cin, int buf) {
        const float* ip = ipbase + (size_t)cin * 4096;
        unsigned sb = inbase + (unsigned)(buf * 18 * 20) * 4u;
        #pragma unroll
        for (int rp = 0; rp < 2; rp++) {
            int r = sr0 + rp * 16;
            if (rp == 0 || r < 18) {
                int iy = i0 - 1 + r;
                bool rowok = (iy >= 0) && (iy < 64);
                const float* iprow = ip + iy * 64;
                unsigned srow = sb + (unsigned)(r * 20) * 4u;
                #pragma unroll
                for (int j = 0; j < 2; j++) {
                    int c = scp + 16 * j;
                    if (j == 0 || c < 18) {
                        int ix = j0 - 1 + c;
                        bool ok = rowok && (ix >= 0) && (ix < 64);
                        const float* ga = ok ? (iprow + ix) : ip;
                        cp_async4(srow + (unsigned)c * 4u, ga, ok);
                    }
                }
            }
        }
        // weights: 128 float2 = 1024B = 64 x 16B
        if (tid < 64)
            cp_async16(wbase + (unsigned)(buf * 128 + tid * 2) * 8u,
                       wgrp + (size_t)cin * 128 + tid * 2);
    };

    issue_stage(0, 0);
    cp_commit();

    for (int cin = 0; cin < 64; ++cin) {
        const int buf = cin & 1;
        if (cin + 1 < 64) issue_stage(cin + 1, (cin + 1) & 1);
        cp_commit();
        cp_wait1();
        __syncthreads();

        float p[3][3];
        #pragma unroll
        for (int r = 0; r < 3; r++)
            #pragma unroll
            for (int c = 0; c < 3; c++)
                p[r][c] = s_in[buf][ty + r][tx + c];
        u64 q[3][2];
        #pragma unroll
        for (int r = 0; r < 3; r++) {
            q[r][0] = pk2(p[r][0], p[r][1]);
            q[r][1] = pk2(p[r][1], p[r][2]);
        }

        #pragma unroll
        for (int i = 0; i < 16; i++) {
            unsigned wa = wbase + (unsigned)(buf * 128) * 8u + i * 64u;
            u64 w[8];
            lds_v2u64(w[0], w[1], wa);
            lds_v2u64(w[2], w[3], wa + 16);
            lds_v2u64(w[4], w[5], wa + 32);
            lds_v2u64(w[6], w[7], wa + 48);
            #pragma unroll
            for (int py = 0; py < 2; py++)
                #pragma unroll
                for (int dr = 0; dr < 2; dr++)
                    #pragma unroll
                    for (int dc = 0; dc < 2; dc++)
                        fma2(acc[i][py], q[py + dr][dc], w[py * 4 + dr * 2 + dc]);
        }
        __syncthreads();
    }

    const int oy2 = 2 * (i0 + ty), ox2 = 2 * (j0 + tx);
    #pragma unroll
    for (int i = 0; i < 16; i++)
        #pragma unroll
        for (int py = 0; py < 2; py++) {
            float v0, v1;
            upk2(acc[i][py], v0, v1);
            v0 = fmaxf(v0, 0.f); v1 = fmaxf(v1, 0.f);
            *reinterpret_cast<float2*>(out + (((size_t)b * 32 + oc0 + i) * 128 + oy2 + py) * 128 + ox2)
                = make_float2(v0, v1);
        }
}

// ------- fused spatial softmax + soft-argmax moments (both streams) -------
__global__ void softmax_mu_kernel(float* __restrict__ p,
                                  float* __restrict__ mu, float* __restrict__ Li,
                                  float* __restrict__ mua, float* __restrict__ Lia)
{
    float* base = p + (size_t)blockIdx.x * 4096;
    __shared__ float red[256];
    int tid = threadIdx.x;
    float m = -1e30f;
    float vals[16];
    #pragma unroll
    for (int j = 0; j < 16; j++) { vals[j] = base[tid + j * 256]; m = fmaxf(m, vals[j]); }
    red[tid] = m; __syncthreads();
    for (int s = 128; s > 0; s >>= 1) { if (tid < s) red[tid] = fmaxf(red[tid], red[tid + s]); __syncthreads(); }
    m = red[0]; __syncthreads();
    float sum = 0.f;
    #pragma unroll
    for (int j = 0; j < 16; j++) { vals[j] = expf(vals[j] - m); sum += vals[j]; }
    float tot = block_sum256(sum, red);
    float inv = 1.f / tot;
    float s0=0,s1=0,s2=0,s3=0,s4=0;
    #pragma unroll
    for (int j = 0; j < 16; j++) {
        int i = tid + j * 256;
        float pv = vals[j] * inv;
        base[i] = pv;
        int h = i >> 6, w = i & 63;
        float gy = -1.f + 2.f * h / 63.f;
        float gx = -1.f + 2.f * w / 63.f;
        s0 += pv * gy; s1 += pv * gx;
        s2 += pv * gy * gy; s3 += pv * gy * gx; s4 += pv * gx * gx;
    }
    s0 = block_sum256(s0, red);
    s1 = block_sum256(s1, red);
    s2 = block_sum256(s2, red);
    s3 = block_sum256(s3, red);
    s4 = block_sum256(s4, red);
    if (tid == 0) {
        float muy = s0, mux = s1;
        float c00 = s2 - muy * muy, c01 = s3 - muy * mux, c11 = s4 - mux * mux;
        float a  = sqrtf(c00 + EPSV);
        float bb = c01 / (a + EPSV);
        float c  = sqrtf(fmaxf(c11 - bb * bb, 0.f) + EPSV);
        float det = a * c;
        float sc = SCALV / (det + EPSV);
        int bk = blockIdx.x;
        float* pmu = (bk < 512) ? mu : mua;
        float* pLi = (bk < 512) ? Li : Lia;
        int o = bk & 511;
        pmu[o * 2 + 0] = muy; pmu[o * 2 + 1] = mux;
        pLi[o * 4 + 0] = sc * c;     pLi[o * 4 + 1] = 0.f;
        pLi[o * 4 + 2] = sc * (-bb); pLi[o * 4 + 3] = sc * a;
    }
}

// ---------------- alpha = einsum('bfhw,bkhw->bkf') ----------------
__global__ void alpha_kernel(const float* __restrict__ fxs,
                             const float* __restrict__ parts,
                             float* __restrict__ alpha)
{
    int bk = blockIdx.x;
    int b = bk >> 4;
    __shared__ float sp[4096];
    __shared__ float red[256];
    int tid = threadIdx.x;
    const float* pb = parts + (size_t)bk * 4096;
    for (int i = tid; i < 4096; i += 256) sp[i] = pb[i];
    __syncthreads();
    for (int f = 0; f < 32; f++) {
        const float* fb = fxs + ((size_t)b * 32 + f) * 4096;
        float s = 0.f;
        for (int i = tid; i < 4096; i += 256) s += fb[i] * sp[i];
        s = block_sum256(s, red);
        if (tid == 0) alpha[(size_t)bk * 32 + f] = s;
    }
}

// ---------------- Cauchy heat render + normalization ----------------
__global__ void heat_kernel(const float* __restrict__ mu, const float* __restrict__ Linv,
                            float* __restrict__ enc, float* __restrict__ norm)
{
    int bk = blockIdx.x;
    int b = bk >> 4, k = bk & 15;
    float muy = mu[bk*2], mux = mu[bk*2+1];
    float L00 = Linv[bk*4], L01 = Linv[bk*4+1], L10 = Linv[bk*4+2], L11 = Linv[bk*4+3];
    int tid = threadIdx.x;
    __shared__ float red[256];
    float hv[16]; float sum = 0.f;
    #pragma unroll
    for (int j = 0; j < 16; j++) {
        int i = tid + j * 256;
        int h = i >> 6, w = i & 63;
        float dy = (-1.f + 2.f * h / 63.f) - muy;
        float dx = (-1.f + 2.f * w / 63.f) - mux;
        float p0 = dy * L00 + dx * L10;
        float p1 = dy * L01 + dx * L11;
        float he = 1.f / (1.f + p0 * p0 + p1 * p1);
        hv[j] = he; sum += he;
    }
    float tot = block_sum256(sum, red);
    float inv = 1.f / (tot + EPSV);
    float* eb = enc + (((size_t)b * 48 + k) * 4096);
    float* nb = norm + (size_t)bk * 4096;
    #pragma unroll
    for (int j = 0; j < 16; j++) {
        int i = tid + j * 256;
        eb[i] = hv[j];
        nb[i] = hv[j] * inv;
    }
}

// ---------------- fmap = einsum('bkf,bkhw->bfhw') -> enc ch [16,48) ----------
__global__ void fmap_kernel(const float* __restrict__ alpha,
                            const float* __restrict__ norm,
                            float* __restrict__ enc)
{
    int b = blockIdx.y;
    int pix = blockIdx.x * 256 + threadIdx.x;
    __shared__ float sal[512];
    for (int i = threadIdx.x; i < 512; i += 256) sal[i] = alpha[(size_t)b * 512 + i];
    __syncthreads();
    float nv[16];
    #pragma unroll
    for (int k = 0; k < 16; k++) nv[k] = norm[((size_t)b * 16 + k) * 4096 + pix];
    #pragma unroll
    for (int f = 0; f < 32; f++) {
        float s = 0.f;
        #pragma unroll
        for (int k = 0; k < 16; k++) s = fmaf(sal[k * 32 + f], nv[k], s);
        enc[((size_t)b * 48 + 16 + f) * 4096 + pix] = s;
    }
}

// ---------------- losses ----------------
__global__ void rec_loss_partial_kernel(const float* __restrict__ x,
                                        const float* __restrict__ rec,
                                        float* __restrict__ partial)
{
    __shared__ float red[256];
    int i0 = blockIdx.x * 1024 + threadIdx.x;
    float s = 0.f;
    #pragma unroll
    for (int j = 0; j < 4; j++) {
        int i = i0 + j * 256;
        float d = x[i] - rec[i];
        s += d * d;
    }
    s = block_sum256(s, red);
    if (threadIdx.x == 0) partial[blockIdx.x] = s;
}

__global__ void final_loss_kernel(const float* __restrict__ partial,
                                  const float* __restrict__ mu, const float* __restrict__ Li,
                                  const float* __restrict__ mua, const float* __restrict__ Lia,
                                  const float* __restrict__ coord, const float* __restrict__ vec,
                                  float* __restrict__ out, int out_size)
{
    __shared__ float red[256];
    int tid = threadIdx.x;
    float s0=0,s1=0,s2=0,s3=0;
    for (int i = tid; i < 1536; i += 256) s0 += partial[i];
    for (int i = tid; i < 1024; i += 256) { float d = mu[i] - mua[i]; s1 += d * d; }
    for (int i = tid; i < 2048; i += 256) { float d = Li[i] - Lia[i]; s2 += d * d; }
    for (int i = tid; i < 1024; i += 256) { float d = mua[i] - (coord[i] + vec[i]); s3 += d * d; }
    s0 = block_sum256(s0, red);
    s1 = block_sum256(s1, red);
    s2 = block_sum256(s2, red);
    s3 = block_sum256(s3, red);
    if (tid == 0) {
        float loss = s0 / 1572864.f + s1 / 1024.f + 0.01f * (s2 / 2048.f) + s3 / 1024.f;
        if (out_size > 1572864) out[1572864] = loss;
    }
}

// ---------------- launch ----------------
extern "C" void kernel_launch(void* const* d_in, const int* in_sizes, int n_in,
                              void* d_out, int out_size)
{
    const float* x     = (const float*)d_in[0];
    const float* xsp   = (const float*)d_in[1];
    const float* xapp  = (const float*)d_in[2];
    const float* coord = (const float*)d_in[3];
    const float* vec   = (const float*)d_in[4];
    const float* es_w1 = (const float*)d_in[5];
    const float* es_b1 = (const float*)d_in[6];
    const float* es_w2 = (const float*)d_in[7];
    const float* es_b2 = (const float*)d_in[8];
    const float* es_wp = (const float*)d_in[9];
    const float* es_bp = (const float*)d_in[10];
    const float* ea_w1 = (const float*)d_in[11];
    const float* ea_b1 = (const float*)d_in[12];
    const float* ea_w2 = (const float*)d_in[13];
    const float* ea_b2 = (const float*)d_in[14];
    const float* d_w1  = (const float*)d_in[15];
    const float* d_b1  = (const float*)d_in[16];
    const float* d_w2  = (const float*)d_in[17];
    const float* d_b2  = (const float*)d_in[18];
    const float* d_w3  = (const float*)d_in[19];
    const float* d_b3  = (const float*)d_in[20];
    float* out = (float*)d_out;

    float *h1,*h2,*t1,*parts,*normb,*fxs,*enc,*h128,*mu,*Li,*mua,*Lia,*al,*part;
    float2 *wc2, *dupw;
    cudaGetSymbolAddress((void**)&h1, g_h1);
    cudaGetSymbolAddress((void**)&h2, g_h2);
    cudaGetSymbolAddress((void**)&t1, g_t1);
    cudaGetSymbolAddress((void**)&parts, g_parts);
    cudaGetSymbolAddress((void**)&normb, g_norm);
    cudaGetSymbolAddress((void**)&fxs, g_fxs);
    cudaGetSymbolAddress((void**)&enc, g_enc);
    cudaGetSymbolAddress((void**)&h128, g_h128);
    cudaGetSymbolAddress((void**)&mu, g_mu);
    cudaGetSymbolAddress((void**)&Li, g_Linv);
    cudaGetSymbolAddress((void**)&mua, g_mua);
    cudaGetSymbolAddress((void**)&Lia, g_Linva);
    cudaGetSymbolAddress((void**)&al, g_alpha);
    cudaGetSymbolAddress((void**)&part, g_partial);
    cudaGetSymbolAddress((void**)&wc2, g_wc2);
    cudaGetSymbolAddress((void**)&dupw, g_dupw);

    const size_t IMG64 = (size_t)64 * 4096;
    const size_t PIMG  = (size_t)16 * 4096;

    dim3 blk(256);

    // ---- weight precomputes (tiny) ----
    wc_precompute_kernel<<<8, blk>>>(d_w2, wc2);
    dup_weights_kernel<<<(64*64*10+255)/256, blk>>>(es_w2, dupw + OFF_ESW2, 64, 64, 16);
    dup_weights_kernel<<<(16*64*10+255)/256, blk>>>(es_wp, dupw + OFF_ESWP, 16, 64, 16);
    dup_weights_kernel<<<(64*64*10+255)/256, blk>>>(ea_w1, dupw + OFF_EAW1, 64, 64, 16);
    dup_weights_kernel<<<(32*64*10+255)/256, blk>>>(ea_w2, dupw + OFF_EAW2, 32, 64, 16);
    dup_weights_kernel<<<(64*48*10+255)/256, blk>>>(d_w1,  dupw + OFF_DW1,  64, 48, 16);
    dup_weights_kernel<<<(3*32*10+255)/256,  blk>>>(d_w3,  dupw + OFF_DW3,   3, 32, 3);

    // ---- merged encoder (batch 64: 0..31 shape/xapp, 32..63 appearance/xsp) ----
    conv_s2_dual<<<dim3(4, 4, 256), blk>>>(xapp, xsp, es_w1, es_b1, h1);
    conv3x3_f2<64,64,16,1><<<dim3(2, 2, 256), blk>>>(h1, dupw + OFF_ESW2, es_b2, h2, 64, 64);
    conv3x3_f2<64,16,16,0><<<dim3(2, 2, 64),  blk>>>(h2, dupw + OFF_ESWP, es_bp, parts, 64, 64);
    softmax_mu_kernel<<<1024, blk>>>(parts, mu, Li, mua, Lia);

    // ---- appearance-only tail ----
    conv3x3_f2<64,64,16,1><<<dim3(2, 2, 128), blk>>>(h2 + BATCH * IMG64, dupw + OFF_EAW1, ea_b1, t1, 64, 64);
    conv3x3_f2<64,32,16,0><<<dim3(2, 2, 64),  blk>>>(t1, dupw + OFF_EAW2, ea_b2, fxs, 64, 64);
    alpha_kernel<<<512, blk>>>(fxs, parts + BATCH * PIMG, al);

    // ---- encoding ----
    heat_kernel<<<512, blk>>>(mu, Li, enc, normb);
    fmap_kernel<<<dim3(16, BATCH), blk>>>(al, normb, enc);

    // ---- decoder ----
    conv3x3_f2<48,64,16,1><<<dim3(2, 2, 128), blk>>>(enc, dupw + OFF_DW1, d_b1, t1, 64, 64);
    parity_conv_kernel<<<dim3(4, 4, 64), blk>>>(t1, wc2, d_b2, h128);
    conv3x3_f2<32,3,3,2><<<dim3(4, 4, 32), blk>>>(h128, dupw + OFF_DW3, d_b3, out, 128, 128);

    // ---- loss ----
    rec_loss_partial_kernel<<<1536, blk>>>(x, out, part);
    final_loss_kernel<<<1, blk>>>(part, mu, Li, mua, Lia, coord, vec, out, out_size);
}

// round 11
// speedup vs baseline: 1.4513x; 1.0874x over previous
#include <cuda_runtime.h>
#include <cuda_bf16.h>
#include <math.h>

#define BATCH 32
#define EPSV 1e-6f
#define SCALV 5.0f

typedef unsigned long long u64;

// ---------------- scratch (static device globals; alloc-free) ----------------
__device__ float g_h1[2*BATCH*64*64*64];
__device__ float g_h2[2*BATCH*64*64*64];
__device__ float g_t1[BATCH*64*64*64];
__device__ float g_parts[2*BATCH*16*64*64];
__device__ float g_norm[BATCH*16*64*64];
__device__ float g_fxs[BATCH*32*64*64];
__device__ float g_enc[BATCH*48*64*64];
__device__ float g_h128[BATCH*32*128*128];
__device__ float g_mu[BATCH*16*2];
__device__ float g_Linv[BATCH*16*4];
__device__ float g_mua[BATCH*16*2];
__device__ float g_Linva[BATCH*16*4];
__device__ float g_alpha[BATCH*16*32];
__device__ float g_partial[1536];
__device__ float2 g_wc2[2*64*16*8];          // parity weights [grp(2)][cin][i(16)][k(8)]

// dup-weight pool (sizes COUT*CIN*10 float2 each), 2-channel chunks
#define OFF_ESW2 0
#define OFF_ESWP (OFF_ESW2 + 64*64*10)
#define OFF_EAW1 (OFF_ESWP + 16*64*10)
#define OFF_EAW2 (OFF_EAW1 + 64*64*10)
#define OFF_DW1  (OFF_EAW2 + 32*64*10)
#define OFF_DW3  (OFF_DW1  + 64*48*10)
#define DUP_TOTAL (OFF_DW3 + 3*32*10)
__device__ float2 g_dupw[DUP_TOTAL];

// ---------------- f32x2 packed helpers ----------------
__device__ __forceinline__ u64 pk2(float lo, float hi) {
    u64 r; asm("mov.b64 %0, {%1, %2};" : "=l"(r) : "f"(lo), "f"(hi)); return r;
}
__device__ __forceinline__ void upk2(u64 v, float& lo, float& hi) {
    asm("mov.b64 {%0, %1}, %2;" : "=f"(lo), "=f"(hi) : "l"(v));
}
__device__ __forceinline__ void fma2(u64& d, u64 a, u64 b) {
    asm("fma.rn.f32x2 %0, %1, %2, %0;" : "+l"(d) : "l"(a), "l"(b));
}
__device__ __forceinline__ unsigned sptr(const void* p) {
    return (unsigned)__cvta_generic_to_shared(p);
}
__device__ __forceinline__ void lds_v2u64(u64& a, u64& b, unsigned addr) {
    asm volatile("ld.shared.v2.u64 {%0, %1}, [%2];" : "=l"(a), "=l"(b) : "r"(addr));
}
__device__ __forceinline__ u64 lds_u64(unsigned addr) {
    u64 r; asm volatile("ld.shared.b64 %0, [%1];" : "=l"(r) : "r"(addr)); return r;
}

// ---------------- cp.async helpers ----------------
__device__ __forceinline__ void cp_async4(unsigned saddr, const void* gaddr, bool ok) {
    asm volatile("cp.async.ca.shared.global [%0], [%1], 4, %2;"
                 :: "r"(saddr), "l"(gaddr), "r"(ok ? 4 : 0));
}
__device__ __forceinline__ void cp_async16(unsigned saddr, const void* gaddr) {
    asm volatile("cp.async.cg.shared.global [%0], [%1], 16;" :: "r"(saddr), "l"(gaddr));
}
__device__ __forceinline__ void cp_commit() {
    asm volatile("cp.async.commit_group;");
}
__device__ __forceinline__ void cp_wait1() {
    asm volatile("cp.async.wait_group 1;");
}

// ---------------- reductions ----------------
__device__ __forceinline__ float warp_sum(float v) {
    #pragma unroll
    for (int o = 16; o; o >>= 1) v += __shfl_xor_sync(0xffffffffu, v, o);
    return v;
}
__device__ __forceinline__ float block_sum256(float v, float* red) {
    int tid = threadIdx.x;
    v = warp_sum(v);
    if ((tid & 31) == 0) red[tid >> 5] = v;
    __syncthreads();
    float r = 0.f;
    if (tid < 8) r = red[tid];
    if (tid < 32) r = warp_sum(r);
    if (tid == 0) red[0] = r;
    __syncthreads();
    float out = red[0];
    __syncthreads();
    return out;
}

// ============ weight duplication precompute (2-channel chunks) ============
__global__ void dup_weights_kernel(const float* __restrict__ src, float2* __restrict__ dst,
                                   int COUT, int CIN, int ACCv)
{
    int total = COUT * CIN * 10;
    int idx = blockIdx.x * 256 + threadIdx.x;
    if (idx >= total) return;
    int k = idx % 10;
    int t = idx / 10;
    int cin = t % CIN;
    int oc  = t / CIN;
    int g = oc / ACCv, i = oc % ACCv;
    int c0h = cin >> 1, cc = cin & 1;
    float w = (k < 9) ? src[((size_t)oc * CIN + cin) * 9 + k] : 0.f;
    dst[((size_t)(g * (CIN >> 1) + c0h) * 2 * ACCv + cc * ACCv + i) * 10 + k] = make_float2(w, w);
}

// ============ pipelined register-blocked packed conv3x3, stride 1, SAME =====
// 32x32 tile, 256 threads, 2x2 outputs/thread, ACC=16 channels,
// cp.async TRIPLE-buffered 2-channel staging, ONE barrier/stage.
template<int CIN, int COUT, int ACC, int ACT>
__global__ __launch_bounds__(256, 2)
void conv3x3_f2(const float* __restrict__ in,
                const float2* __restrict__ dupw,
                const float* __restrict__ bias,
                float* __restrict__ out, int OH, int OW)
{
    __shared__ float s_in[3][2][34][36];                  // [buf][cc][r][c]
    __shared__ __align__(16) float2 s_w[3][2 * ACC * 10]; // [buf][...]

    constexpr int GROUPS = COUT / ACC;
    constexpr int NS = CIN / 2;
    const int b   = blockIdx.z / GROUPS;
    const int grp = blockIdx.z % GROUPS;
    const int oc0 = grp * ACC;
    const int tid = threadIdx.x;
    const int tx = tid & 15, ty = tid >> 4;
    const int oy0 = blockIdx.y * 32, ox0 = blockIdx.x * 32;

    const int sr0 = tid >> 3;
    const int sc0 = tid & 7;

    u64 acc[ACC][2];
    #pragma unroll
    for (int i = 0; i < ACC; i++) {
        float bv = bias[oc0 + i];
        acc[i][0] = pk2(bv, bv);
        acc[i][1] = acc[i][0];
    }

    const unsigned inbase = sptr(&s_in[0][0][0][0]);
    const unsigned wbase  = sptr(&s_w[0][0]);
    const float2* wchunk = dupw + (size_t)grp * (CIN >> 1) * (2 * ACC * 10);
    const float* ipbase = in + (size_t)b * CIN * OH * OW;

    auto issue_stage = [&](int s) {
        const int buf = s % 3;
        const int c0 = 2 * s;
        #pragma unroll
        for (int cc = 0; cc < 2; cc++) {
            const float* ip = ipbase + (size_t)(c0 + cc) * OH * OW;
            unsigned sb = inbase + (unsigned)((buf * 2 + cc) * 34 * 36) * 4u;
            #pragma unroll
            for (int rp = 0; rp < 2; rp++) {
                int r = sr0 + rp * 32;
                if (rp == 0 || r < 34) {
                    int iy = oy0 - 1 + r;
                    bool rowok = (iy >= 0) && (iy < OH);
                    const float* iprow = ip + iy * OW;
                    unsigned srow = sb + (unsigned)(r * 36) * 4u;
                    #pragma unroll
                    for (int j = 0; j < 5; j++) {
                        int c = sc0 + 8 * j;
                        if (j < 4 || c < 34) {
                            int ix = ox0 - 1 + c;
                            bool ok = rowok && (ix >= 0) && (ix < OW);
                            const float* ga = ok ? (iprow + ix) : ip;
                            cp_async4(srow + (unsigned)c * 4u, ga, ok);
                        }
                    }
                }
            }
        }
        if (tid < ACC * 10) {
            const float2* wsrc = wchunk + (size_t)(c0 >> 1) * (2 * ACC * 10);
            cp_async16(wbase + (unsigned)(buf * 2 * ACC * 10 + tid * 2) * 8u,
                       wsrc + tid * 2);
        }
    };

    issue_stage(0); cp_commit();
    issue_stage(1); cp_commit();

    for (int s = 0; s < NS; s++) {
        const int buf = s % 3;
        cp_wait1();            // stage s complete (only group s+1 may be outstanding)
        __syncthreads();       // single barrier per stage

        #pragma unroll
        for (int cc = 0; cc < 2; cc++) {
            u64 pr[4][3];
            #pragma unroll
            for (int r = 0; r < 4; r++) {
                unsigned a = inbase + (unsigned)((buf * 2 + cc) * 34 * 36 + (2 * ty + r) * 36 + 2 * tx) * 4u;
                u64 A = lds_u64(a);
                u64 B = lds_u64(a + 8);
                float a0, a1, b0, b1;
                upk2(A, a0, a1); upk2(B, b0, b1);
                pr[r][0] = A; pr[r][1] = pk2(a1, b0); pr[r][2] = B;
            }
            #pragma unroll
            for (int i = 0; i < ACC; i++) {
                unsigned wa = wbase + (unsigned)(buf * 2 * ACC * 10) * 8u
                            + (unsigned)(cc * ACC + i) * 80u;
                u64 w[9];
                lds_v2u64(w[0], w[1], wa);
                lds_v2u64(w[2], w[3], wa + 16);
                lds_v2u64(w[4], w[5], wa + 32);
                lds_v2u64(w[6], w[7], wa + 48);
                w[8] = lds_u64(wa + 64);
                #pragma unroll
                for (int dy = 0; dy < 2; dy++)
                    #pragma unroll
                    for (int ky = 0; ky < 3; ky++)
                        #pragma unroll
                        for (int kx = 0; kx < 3; kx++)
                            fma2(acc[i][dy], pr[dy + ky][kx], w[ky * 3 + kx]);
            }
        }
        // issue stage s+2 into buffer (s+2)%3 == (s-1)%3: safe — all threads are
        // past the stage-s barrier, so none is still reading stage s-1.
        if (s + 2 < NS) issue_stage(s + 2);
        cp_commit();           // empty group when nothing issued keeps ledger aligned
    }

    const int oy = oy0 + 2 * ty, ox = ox0 + 2 * tx;
    #pragma unroll
    for (int i = 0; i < ACC; i++)
        #pragma unroll
        for (int dy = 0; dy < 2; dy++) {
            float v0, v1;
            upk2(acc[i][dy], v0, v1);
            if (ACT == 1) { v0 = fmaxf(v0, 0.f); v1 = fmaxf(v1, 0.f); }
            else if (ACT == 2) { v0 = 1.f / (1.f + expf(-v0)); v1 = 1.f / (1.f + expf(-v1)); }
            *reinterpret_cast<float2*>(out + (((size_t)b * COUT + oc0 + i) * OH + oy + dy) * OW + ox)
                = make_float2(v0, v1);
        }
}

// ============ dual-input stride-2 conv 3->64 ====
__global__ void conv_s2_dual(const float* __restrict__ inA,
                             const float* __restrict__ inB,
                             const float* __restrict__ wt,
                             const float* __restrict__ bias,
                             float* __restrict__ out)
{
    constexpr int TS = 16, IT = TS * 2 + 2;
    __shared__ float s_in[IT][IT];
    __shared__ float s_w[16 * 9];

    const int b   = blockIdx.z >> 2;
    const int oc0 = (blockIdx.z & 3) * 16;
    const float* in = (b < BATCH) ? inA + (size_t)b * 3 * 128 * 128
                                  : inB + (size_t)(b - BATCH) * 3 * 128 * 128;
    const int tid = threadIdx.x;
    const int tx = tid & 15, ty = tid >> 4;
    const int ox = blockIdx.x * TS + tx;
    const int oy = blockIdx.y * TS + ty;
    const int iy0 = blockIdx.y * TS * 2;
    const int ix0 = blockIdx.x * TS * 2;

    float acc[16];
    #pragma unroll
    for (int i = 0; i < 16; i++) acc[i] = bias[oc0 + i];

    for (int cin = 0; cin < 3; ++cin) {
        const float* ip = in + (size_t)cin * 128 * 128;
        for (int idx = tid; idx < IT * IT; idx += 256) {
            int r = idx / IT, c = idx % IT;
            int iy = iy0 + r, ix = ix0 + c;
            float v = 0.f;
            if (iy < 128 && ix < 128) v = ip[iy * 128 + ix];
            s_in[r][c] = v;
        }
        if (tid < 16 * 9)
            s_w[tid] = wt[((oc0 + tid / 9) * 3 + cin) * 9 + (tid % 9)];
        __syncthreads();

        #pragma unroll
        for (int ky = 0; ky < 3; ky++)
            #pragma unroll
            for (int kx = 0; kx < 3; kx++) {
                float v = s_in[ty * 2 + ky][tx * 2 + kx];
                #pragma unroll
                for (int i = 0; i < 16; i++)
                    acc[i] = fmaf(v, s_w[i * 9 + ky * 3 + kx], acc[i]);
            }
        __syncthreads();
    }

    #pragma unroll
    for (int i = 0; i < 16; i++)
        out[(((size_t)b * 64 + oc0 + i) * 64 + oy) * 64 + ox] = fmaxf(acc[i], 0.f);
}

// ============ parity-combined weights for upsample conv (d_w2) ============
__global__ void wc_precompute_kernel(const float* __restrict__ w2, float2* __restrict__ wc2)
{
    int t = blockIdx.x * 256 + threadIdx.x;
    if (t >= 32 * 64) return;
    int oc = t / 64, cin = t % 64;
    int grp = oc >> 4, i = oc & 15;
    float w[3][3];
    #pragma unroll
    for (int r = 0; r < 3; r++)
        #pragma unroll
        for (int c = 0; c < 3; c++)
            w[r][c] = w2[t * 9 + r * 3 + c];
    float ry[2][2][3];
    #pragma unroll
    for (int c = 0; c < 3; c++) {
        ry[0][0][c] = w[0][c];
        ry[0][1][c] = w[1][c] + w[2][c];
        ry[1][0][c] = w[0][c] + w[1][c];
        ry[1][1][c] = w[2][c];
    }
    float2* dst = wc2 + ((size_t)(grp * 64 + cin) * 16 + i) * 8;
    #pragma unroll
    for (int py = 0; py < 2; py++)
        #pragma unroll
        for (int dr = 0; dr < 2; dr++)
            #pragma unroll
            for (int dc = 0; dc < 2; dc++) {
                float v_px0 = (dc == 0) ? ry[py][dr][0] : (ry[py][dr][1] + ry[py][dr][2]);
                float v_px1 = (dc == 0) ? (ry[py][dr][0] + ry[py][dr][1]) : ry[py][dr][2];
                dst[py * 4 + dr * 2 + dc] = make_float2(v_px0, v_px1);
            }
}

// ============ pipelined parity conv: triple-buffered, one barrier/stage ======
__global__ __launch_bounds__(256, 2)
void parity_conv_kernel(const float* __restrict__ in,
                        const float2* __restrict__ wc2,
                        const float* __restrict__ bias,
                        float* __restrict__ out)
{
    __shared__ float s_in[3][18][20];
    __shared__ __align__(16) float2 s_w[3][128];

    const int b   = blockIdx.z >> 1;
    const int grp = blockIdx.z & 1;
    const int oc0 = grp * 16;
    const int tid = threadIdx.x;
    const int tx = tid & 15, ty = tid >> 4;
    const int i0 = blockIdx.y * 16, j0 = blockIdx.x * 16;

    const int sr0 = tid >> 4;
    const int scp = tid & 15;

    u64 acc[16][2];
    #pragma unroll
    for (int i = 0; i < 16; i++) {
        float bv = bias[oc0 + i];
        acc[i][0] = pk2(bv, bv);
        acc[i][1] = acc[i][0];
    }
    const unsigned inbase = sptr(&s_in[0][0][0]);
    const unsigned wbase = sptr(&s_w[0][0]);
    const float* ipbase = in + (size_t)b * 64 * 4096;
    const float2* wgrp = wc2 + (size_t)grp * 64 * 128;

    auto issue_stage = [&](int cin) {
        const int buf = cin % 3;
        const float* ip = ipbase + (size_t)cin * 4096;
        unsigned sb = inbase + (unsigned)(buf * 18 * 20) * 4u;
        #pragma unroll
        for (int rp = 0; rp < 2; rp++) {
            int r = sr0 + rp * 16;
            if (rp == 0 || r < 18) {
                int iy = i0 - 1 + r;
                bool rowok = (iy >= 0) && (iy < 64);
                const float* iprow = ip + iy * 64;
                unsigned srow = sb + (unsigned)(r * 20) * 4u;
                #pragma unroll
                for (int j = 0; j < 2; j++) {
                    int c = scp + 16 * j;
                    if (j == 0 || c < 18) {
                        int ix = j0 - 1 + c;
                        bool ok = rowok && (ix >= 0) && (ix < 64);
                        const float* ga = ok ? (iprow + ix) : ip;
                        cp_async4(srow + (unsigned)c * 4u, ga, ok);
                    }
                }
            }
        }
        if (tid < 64)
            cp_async16(wbase + (unsigned)(buf * 128 + tid * 2) * 8u,
                       wgrp + (size_t)cin * 128 + tid * 2);
    };

    issue_stage(0); cp_commit();
    issue_stage(1); cp_commit();

    for (int cin = 0; cin < 64; ++cin) {
        const int buf = cin % 3;
        cp_wait1();
        __syncthreads();

        float p[3][3];
        #pragma unroll
        for (int r = 0; r < 3; r++)
            #pragma unroll
            for (int c = 0; c < 3; c++)
                p[r][c] = s_in[buf][ty + r][tx + c];
        u64 q[3][2];
        #pragma unroll
        for (int r = 0; r < 3; r++) {
            q[r][0] = pk2(p[r][0], p[r][1]);
            q[r][1] = pk2(p[r][1], p[r][2]);
        }

        #pragma unroll
        for (int i = 0; i < 16; i++) {
            unsigned wa = wbase + (unsigned)(buf * 128) * 8u + i * 64u;
            u64 w[8];
            lds_v2u64(w[0], w[1], wa);
            lds_v2u64(w[2], w[3], wa + 16);
            lds_v2u64(w[4], w[5], wa + 32);
            lds_v2u64(w[6], w[7], wa + 48);
            #pragma unroll
            for (int py = 0; py < 2; py++)
                #pragma unroll
                for (int dr = 0; dr < 2; dr++)
                    #pragma unroll
                    for (int dc = 0; dc < 2; dc++)
                        fma2(acc[i][py], q[py + dr][dc], w[py * 4 + dr * 2 + dc]);
        }
        if (cin + 2 < 64) issue_stage(cin + 2);
        cp_commit();
    }

    const int oy2 = 2 * (i0 + ty), ox2 = 2 * (j0 + tx);
    #pragma unroll
    for (int i = 0; i < 16; i++)
        #pragma unroll
        for (int py = 0; py < 2; py++) {
            float v0, v1;
            upk2(acc[i][py], v0, v1);
            v0 = fmaxf(v0, 0.f); v1 = fmaxf(v1, 0.f);
            *reinterpret_cast<float2*>(out + (((size_t)b * 32 + oc0 + i) * 128 + oy2 + py) * 128 + ox2)
                = make_float2(v0, v1);
        }
}

// ------- fused spatial softmax + soft-argmax moments (both streams) -------
__global__ void softmax_mu_kernel(float* __restrict__ p,
                                  float* __restrict__ mu, float* __restrict__ Li,
                                  float* __restrict__ mua, float* __restrict__ Lia)
{
    float* base = p + (size_t)blockIdx.x * 4096;
    __shared__ float red[256];
    int tid = threadIdx.x;
    float m = -1e30f;
    float vals[16];
    #pragma unroll
    for (int j = 0; j < 16; j++) { vals[j] = base[tid + j * 256]; m = fmaxf(m, vals[j]); }
    red[tid] = m; __syncthreads();
    for (int s = 128; s > 0; s >>= 1) { if (tid < s) red[tid] = fmaxf(red[tid], red[tid + s]); __syncthreads(); }
    m = red[0]; __syncthreads();
    float sum = 0.f;
    #pragma unroll
    for (int j = 0; j < 16; j++) { vals[j] = expf(vals[j] - m); sum += vals[j]; }
    float tot = block_sum256(sum, red);
    float inv = 1.f / tot;
    float s0=0,s1=0,s2=0,s3=0,s4=0;
    #pragma unroll
    for (int j = 0; j < 16; j++) {
        int i = tid + j * 256;
        float pv = vals[j] * inv;
        base[i] = pv;
        int h = i >> 6, w = i & 63;
        float gy = -1.f + 2.f * h / 63.f;
        float gx = -1.f + 2.f * w / 63.f;
        s0 += pv * gy; s1 += pv * gx;
        s2 += pv * gy * gy; s3 += pv * gy * gx; s4 += pv * gx * gx;
    }
    s0 = block_sum256(s0, red);
    s1 = block_sum256(s1, red);
    s2 = block_sum256(s2, red);
    s3 = block_sum256(s3, red);
    s4 = block_sum256(s4, red);
    if (tid == 0) {
        float muy = s0, mux = s1;
        float c00 = s2 - muy * muy, c01 = s3 - muy * mux, c11 = s4 - mux * mux;
        float a  = sqrtf(c00 + EPSV);
        float bb = c01 / (a + EPSV);
        float c  = sqrtf(fmaxf(c11 - bb * bb, 0.f) + EPSV);
        float det = a * c;
        float sc = SCALV / (det + EPSV);
        int bk = blockIdx.x;
        float* pmu = (bk < 512) ? mu : mua;
        float* pLi = (bk < 512) ? Li : Lia;
        int o = bk & 511;
        pmu[o * 2 + 0] = muy; pmu[o * 2 + 1] = mux;
        pLi[o * 4 + 0] = sc * c;     pLi[o * 4 + 1] = 0.f;
        pLi[o * 4 + 2] = sc * (-bb); pLi[o * 4 + 3] = sc * a;
    }
}

// ---------------- alpha = einsum('bfhw,bkhw->bkf') ----------------
__global__ void alpha_kernel(const float* __restrict__ fxs,
                             const float* __restrict__ parts,
                             float* __restrict__ alpha)
{
    int bk = blockIdx.x;
    int b = bk >> 4;
    __shared__ float sp[4096];
    __shared__ float red[256];
    int tid = threadIdx.x;
    const float* pb = parts + (size_t)bk * 4096;
    for (int i = tid; i < 4096; i += 256) sp[i] = pb[i];
    __syncthreads();
    for (int f = 0; f < 32; f++) {
        const float* fb = fxs + ((size_t)b * 32 + f) * 4096;
        float s = 0.f;
        for (int i = tid; i < 4096; i += 256) s += fb[i] * sp[i];
        s = block_sum256(s, red);
        if (tid == 0) alpha[(size_t)bk * 32 + f] = s;
    }
}

// ---------------- Cauchy heat render + normalization ----------------
__global__ void heat_kernel(const float* __restrict__ mu, const float* __restrict__ Linv,
                            float* __restrict__ enc, float* __restrict__ norm)
{
    int bk = blockIdx.x;
    int b = bk >> 4, k = bk & 15;
    float muy = mu[bk*2], mux = mu[bk*2+1];
    float L00 = Linv[bk*4], L01 = Linv[bk*4+1], L10 = Linv[bk*4+2], L11 = Linv[bk*4+3];
    int tid = threadIdx.x;
    __shared__ float red[256];
    float hv[16]; float sum = 0.f;
    #pragma unroll
    for (int j = 0; j < 16; j++) {
        int i = tid + j * 256;
        int h = i >> 6, w = i & 63;
        float dy = (-1.f + 2.f * h / 63.f) - muy;
        float dx = (-1.f + 2.f * w / 63.f) - mux;
        float p0 = dy * L00 + dx * L10;
        float p1 = dy * L01 + dx * L11;
        float he = 1.f / (1.f + p0 * p0 + p1 * p1);
        hv[j] = he; sum += he;
    }
    float tot = block_sum256(sum, red);
    float inv = 1.f / (tot + EPSV);
    float* eb = enc + (((size_t)b * 48 + k) * 4096);
    float* nb = norm + (size_t)bk * 4096;
    #pragma unroll
    for (int j = 0; j < 16; j++) {
        int i = tid + j * 256;
        eb[i] = hv[j];
        nb[i] = hv[j] * inv;
    }
}

// ---------------- fmap = einsum('bkf,bkhw->bfhw') -> enc ch [16,48) ----------
__global__ void fmap_kernel(const float* __restrict__ alpha,
                            const float* __restrict__ norm,
                            float* __restrict__ enc)
{
    int b = blockIdx.y;
    int pix = blockIdx.x * 256 + threadIdx.x;
    __shared__ float sal[512];
    for (int i = threadIdx.x; i < 512; i += 256) sal[i] = alpha[(size_t)b * 512 + i];
    __syncthreads();
    float nv[16];
    #pragma unroll
    for (int k = 0; k < 16; k++) nv[k] = norm[((size_t)b * 16 + k) * 4096 + pix];
    #pragma unroll
    for (int f = 0; f < 32; f++) {
        float s = 0.f;
        #pragma unroll
        for (int k = 0; k < 16; k++) s = fmaf(sal[k * 32 + f], nv[k], s);
        enc[((size_t)b * 48 + 16 + f) * 4096 + pix] = s;
    }
}

// ---------------- losses ----------------
__global__ void rec_loss_partial_kernel(const float* __restrict__ x,
                                        const float* __restrict__ rec,
                                        float* __restrict__ partial)
{
    __shared__ float red[256];
    int i0 = blockIdx.x * 1024 + threadIdx.x;
    float s = 0.f;
    #pragma unroll
    for (int j = 0; j < 4; j++) {
        int i = i0 + j * 256;
        float d = x[i] - rec[i];
        s += d * d;
    }
    s = block_sum256(s, red);
    if (threadIdx.x == 0) partial[blockIdx.x] = s;
}

__global__ void final_loss_kernel(const float* __restrict__ partial,
                                  const float* __restrict__ mu, const float* __restrict__ Li,
                                  const float* __restrict__ mua, const float* __restrict__ Lia,
                                  const float* __restrict__ coord, const float* __restrict__ vec,
                                  float* __restrict__ out, int out_size)
{
    __shared__ float red[256];
    int tid = threadIdx.x;
    float s0=0,s1=0,s2=0,s3=0;
    for (int i = tid; i < 1536; i += 256) s0 += partial[i];
    for (int i = tid; i < 1024; i += 256) { float d = mu[i] - mua[i]; s1 += d * d; }
    for (int i = tid; i < 2048; i += 256) { float d = Li[i] - Lia[i]; s2 += d * d; }
    for (int i = tid; i < 1024; i += 256) { float d = mua[i] - (coord[i] + vec[i]); s3 += d * d; }
    s0 = block_sum256(s0, red);
    s1 = block_sum256(s1, red);
    s2 = block_sum256(s2, red);
    s3 = block_sum256(s3, red);
    if (tid == 0) {
        float loss = s0 / 1572864.f + s1 / 1024.f + 0.01f * (s2 / 2048.f) + s3 / 1024.f;
        if (out_size > 1572864) out[1572864] = loss;
    }
}

// ---------------- launch ----------------
extern "C" void kernel_launch(void* const* d_in, const int* in_sizes, int n_in,
                              void* d_out, int out_size)
{
    const float* x     = (const float*)d_in[0];
    const float* xsp   = (const float*)d_in[1];
    const float* xapp  = (const float*)d_in[2];
    const float* coord = (const float*)d_in[3];
    const float* vec   = (const float*)d_in[4];
    const float* es_w1 = (const float*)d_in[5];
    const float* es_b1 = (const float*)d_in[6];
    const float* es_w2 = (const float*)d_in[7];
    const float* es_b2 = (const float*)d_in[8];
    const float* es_wp = (const float*)d_in[9];
    const float* es_bp = (const float*)d_in[10];
    const float* ea_w1 = (const float*)d_in[11];
    const float* ea_b1 = (const float*)d_in[12];
    const float* ea_w2 = (const float*)d_in[13];
    const float* ea_b2 = (const float*)d_in[14];
    const float* d_w1  = (const float*)d_in[15];
    const float* d_b1  = (const float*)d_in[16];
    const float* d_w2  = (const float*)d_in[17];
    const float* d_b2  = (const float*)d_in[18];
    const float* d_w3  = (const float*)d_in[19];
    const float* d_b3  = (const float*)d_in[20];
    float* out = (float*)d_out;

    float *h1,*h2,*t1,*parts,*normb,*fxs,*enc,*h128,*mu,*Li,*mua,*Lia,*al,*part;
    float2 *wc2, *dupw;
    cudaGetSymbolAddress((void**)&h1, g_h1);
    cudaGetSymbolAddress((void**)&h2, g_h2);
    cudaGetSymbolAddress((void**)&t1, g_t1);
    cudaGetSymbolAddress((void**)&parts, g_parts);
    cudaGetSymbolAddress((void**)&normb, g_norm);
    cudaGetSymbolAddress((void**)&fxs, g_fxs);
    cudaGetSymbolAddress((void**)&enc, g_enc);
    cudaGetSymbolAddress((void**)&h128, g_h128);
    cudaGetSymbolAddress((void**)&mu, g_mu);
    cudaGetSymbolAddress((void**)&Li, g_Linv);
    cudaGetSymbolAddress((void**)&mua, g_mua);
    cudaGetSymbolAddress((void**)&Lia, g_Linva);
    cudaGetSymbolAddress((void**)&al, g_alpha);
    cudaGetSymbolAddress((void**)&part, g_partial);
    cudaGetSymbolAddress((void**)&wc2, g_wc2);
    cudaGetSymbolAddress((void**)&dupw, g_dupw);

    const size_t IMG64 = (size_t)64 * 4096;
    const size_t PIMG  = (size_t)16 * 4096;

    dim3 blk(256);

    // Launch order arranged so the 6th launch is the hot 64->64 conv (ncu -s 5 -c 1).
    dup_weights_kernel<<<(64*64*10+255)/256, blk>>>(es_w2, dupw + OFF_ESW2, 64, 64, 16);   // 1
    wc_precompute_kernel<<<8, blk>>>(d_w2, wc2);                                            // 2
    dup_weights_kernel<<<(16*64*10+255)/256, blk>>>(es_wp, dupw + OFF_ESWP, 16, 64, 16);   // 3
    conv_s2_dual<<<dim3(4, 4, 256), blk>>>(xapp, xsp, es_w1, es_b1, h1);                    // 4
    dup_weights_kernel<<<(64*64*10+255)/256, blk>>>(ea_w1, dupw + OFF_EAW1, 64, 64, 16);   // 5
    conv3x3_f2<64,64,16,1><<<dim3(2, 2, 256), blk>>>(h1, dupw + OFF_ESW2, es_b2, h2, 64, 64); // 6 <- profiled
    dup_weights_kernel<<<(32*64*10+255)/256, blk>>>(ea_w2, dupw + OFF_EAW2, 32, 64, 16);
    dup_weights_kernel<<<(64*48*10+255)/256, blk>>>(d_w1,  dupw + OFF_DW1,  64, 48, 16);
    dup_weights_kernel<<<(3*32*10+255)/256,  blk>>>(d_w3,  dupw + OFF_DW3,   3, 32, 3);

    conv3x3_f2<64,16,16,0><<<dim3(2, 2, 64),  blk>>>(h2, dupw + OFF_ESWP, es_bp, parts, 64, 64);
    softmax_mu_kernel<<<1024, blk>>>(parts, mu, Li, mua, Lia);

    // ---- appearance-only tail ----
    conv3x3_f2<64,64,16,1><<<dim3(2, 2, 128), blk>>>(h2 + BATCH * IMG64, dupw + OFF_EAW1, ea_b1, t1, 64, 64);
    conv3x3_f2<64,32,16,0><<<dim3(2, 2, 64),  blk>>>(t1, dupw + OFF_EAW2, ea_b2, fxs, 64, 64);
    alpha_kernel<<<512, blk>>>(fxs, parts + BATCH * PIMG, al);

    // ---- encoding ----
    heat_kernel<<<512, blk>>>(mu, Li, enc, normb);
    fmap_kernel<<<dim3(16, BATCH), blk>>>(al, normb, enc);

    // ---- decoder ----
    conv3x3_f2<48,64,16,1><<<dim3(2, 2, 128), blk>>>(enc, dupw + OFF_DW1, d_b1, t1, 64, 64);
    parity_conv_kernel<<<dim3(4, 4, 64), blk>>>(t1, wc2, d_b2, h128);
    conv3x3_f2<32,3,3,2><<<dim3(4, 4, 32), blk>>>(h128, dupw + OFF_DW3, d_b3, out, 128, 128);

    // ---- loss ----
    rec_loss_partial_kernel<<<1536, blk>>>(x, out, part);
    final_loss_kernel<<<1, blk>>>(part, mu, Li, mua, Lia, coord, vec, out, out_size);
}

// round 15
// speedup vs baseline: 1.4851x; 1.0233x over previous
#include <cuda_runtime.h>
#include <cuda_bf16.h>
#include <math.h>

#define BATCH 32
#define EPSV 1e-6f
#define SCALV 5.0f

typedef unsigned long long u64;

// ---------------- scratch (static device globals; alloc-free) ----------------
__device__ float g_h1[2*BATCH*64*64*64];
__device__ float g_h2[2*BATCH*64*64*64];
__device__ float g_t1[BATCH*64*64*64];
__device__ float g_parts[2*BATCH*16*64*64];
__device__ float g_norm[BATCH*16*64*64];
__device__ float g_fxs[BATCH*32*64*64];
__device__ float g_enc[BATCH*48*64*64];
__device__ float g_h128[BATCH*32*128*128];
__device__ float g_mu[BATCH*16*2];
__device__ float g_Linv[BATCH*16*4];
__device__ float g_mua[BATCH*16*2];
__device__ float g_Linva[BATCH*16*4];
__device__ float g_alpha[BATCH*16*32];
__device__ float g_partial[1536];
__device__ float2 g_wc2[2*64*16*8];          // parity weights [grp(2)][cin][i(16)][k(8)]

// dup-weight pool (sizes COUT*CIN*10 float2 each), 2-channel chunks
#define OFF_ESW2 0
#define OFF_ESWP (OFF_ESW2 + 64*64*10)
#define OFF_EAW1 (OFF_ESWP + 16*64*10)
#define OFF_EAW2 (OFF_EAW1 + 64*64*10)
#define OFF_DW1  (OFF_EAW2 + 32*64*10)
#define OFF_DW3  (OFF_DW1  + 64*48*10)
#define DUP_TOTAL (OFF_DW3 + 3*32*10)
__device__ float2 g_dupw[DUP_TOTAL];

// ---------------- f32x2 packed helpers ----------------
__device__ __forceinline__ u64 pk2(float lo, float hi) {
    u64 r; asm("mov.b64 %0, {%1, %2};" : "=l"(r) : "f"(lo), "f"(hi)); return r;
}
__device__ __forceinline__ void upk2(u64 v, float& lo, float& hi) {
    asm("mov.b64 {%0, %1}, %2;" : "=f"(lo), "=f"(hi) : "l"(v));
}
__device__ __forceinline__ void fma2(u64& d, u64 a, u64 b) {
    asm("fma.rn.f32x2 %0, %1, %2, %0;" : "+l"(d) : "l"(a), "l"(b));
}
__device__ __forceinline__ unsigned sptr(const void* p) {
    return (unsigned)__cvta_generic_to_shared(p);
}
__device__ __forceinline__ void lds_v2u64(u64& a, u64& b, unsigned addr) {
    asm volatile("ld.shared.v2.u64 {%0, %1}, [%2];" : "=l"(a), "=l"(b) : "r"(addr));
}
__device__ __forceinline__ u64 lds_u64(unsigned addr) {
    u64 r; asm volatile("ld.shared.b64 %0, [%1];" : "=l"(r) : "r"(addr)); return r;
}

// ---------------- cp.async helpers ----------------
__device__ __forceinline__ void cp_async4(unsigned saddr, const void* gaddr, bool ok) {
    asm volatile("cp.async.ca.shared.global [%0], [%1], 4, %2;"
                 :: "r"(saddr), "l"(gaddr), "r"(ok ? 4 : 0));
}
__device__ __forceinline__ void cp_async16(unsigned saddr, const void* gaddr) {
    asm volatile("cp.async.cg.shared.global [%0], [%1], 16;" :: "r"(saddr), "l"(gaddr));
}
__device__ __forceinline__ void cp_commit() {
    asm volatile("cp.async.commit_group;");
}
__device__ __forceinline__ void cp_wait1() {
    asm volatile("cp.async.wait_group 1;");
}
__device__ __forceinline__ void cp_wait0() {
    asm volatile("cp.async.wait_group 0;");
}

// ---------------- reductions ----------------
__device__ __forceinline__ float warp_sum(float v) {
    #pragma unroll
    for (int o = 16; o; o >>= 1) v += __shfl_xor_sync(0xffffffffu, v, o);
    return v;
}
__device__ __forceinline__ float block_sum256(float v, float* red) {
    int tid = threadIdx.x;
    v = warp_sum(v);
    if ((tid & 31) == 0) red[tid >> 5] = v;
    __syncthreads();
    float r = 0.f;
    if (tid < 8) r = red[tid];
    if (tid < 32) r = warp_sum(r);
    if (tid == 0) red[0] = r;
    __syncthreads();
    float out = red[0];
    __syncthreads();
    return out;
}

// ============ weight duplication precompute (2-channel chunks) ============
__global__ void dup_weights_kernel(const float* __restrict__ src, float2* __restrict__ dst,
                                   int COUT, int CIN, int ACCv)
{
    int total = COUT * CIN * 10;
    int idx = blockIdx.x * 256 + threadIdx.x;
    if (idx >= total) return;
    int k = idx % 10;
    int t = idx / 10;
    int cin = t % CIN;
    int oc  = t / CIN;
    int g = oc / ACCv, i = oc % ACCv;
    int c0h = cin >> 1, cc = cin & 1;
    float w = (k < 9) ? src[((size_t)oc * CIN + cin) * 9 + k] : 0.f;
    dst[((size_t)(g * (CIN >> 1) + c0h) * 2 * ACCv + cc * ACCv + i) * 10 + k] = make_float2(w, w);
}

// ============ pipelined register-blocked packed conv3x3, stride 1, SAME =====
// 32x32 tile, 256 threads, 2x2 outputs/thread, ACC=16 channels,
// cp.async TRIPLE-buffered 2-channel staging, ONE barrier/stage.
template<int CIN, int COUT, int ACC, int ACT>
__global__ __launch_bounds__(256, 2)
void conv3x3_f2(const float* __restrict__ in,
                const float2* __restrict__ dupw,
                const float* __restrict__ bias,
                float* __restrict__ out, int OH, int OW)
{
    __shared__ float s_in[3][2][34][36];                  // [buf][cc][r][c]
    __shared__ __align__(16) float2 s_w[3][2 * ACC * 10]; // [buf][...]

    constexpr int GROUPS = COUT / ACC;
    constexpr int NS = CIN / 2;
    const int b   = blockIdx.z / GROUPS;
    const int grp = blockIdx.z % GROUPS;
    const int oc0 = grp * ACC;
    const int tid = threadIdx.x;
    const int tx = tid & 15, ty = tid >> 4;
    const int oy0 = blockIdx.y * 32, ox0 = blockIdx.x * 32;

    const int sr0 = tid >> 3;
    const int sc0 = tid & 7;

    u64 acc[ACC][2];
    #pragma unroll
    for (int i = 0; i < ACC; i++) {
        float bv = bias[oc0 + i];
        acc[i][0] = pk2(bv, bv);
        acc[i][1] = acc[i][0];
    }

    const unsigned inbase = sptr(&s_in[0][0][0][0]);
    const unsigned wbase  = sptr(&s_w[0][0]);
    const float2* wchunk = dupw + (size_t)grp * (CIN >> 1) * (2 * ACC * 10);
    const float* ipbase = in + (size_t)b * CIN * OH * OW;

    auto issue_stage = [&](int s) {
        const int buf = s % 3;
        const int c0 = 2 * s;
        #pragma unroll
        for (int cc = 0; cc < 2; cc++) {
            const float* ip = ipbase + (size_t)(c0 + cc) * OH * OW;
            unsigned sb = inbase + (unsigned)((buf * 2 + cc) * 34 * 36) * 4u;
            #pragma unroll
            for (int rp = 0; rp < 2; rp++) {
                int r = sr0 + rp * 32;
                if (rp == 0 || r < 34) {
                    int iy = oy0 - 1 + r;
                    bool rowok = (iy >= 0) && (iy < OH);
                    const float* iprow = ip + iy * OW;
                    unsigned srow = sb + (unsigned)(r * 36) * 4u;
                    #pragma unroll
                    for (int j = 0; j < 5; j++) {
                        int c = sc0 + 8 * j;
                        if (j < 4 || c < 34) {
                            int ix = ox0 - 1 + c;
                            bool ok = rowok && (ix >= 0) && (ix < OW);
                            const float* ga = ok ? (iprow + ix) : ip;
                            cp_async4(srow + (unsigned)c * 4u, ga, ok);
                        }
                    }
                }
            }
        }
        if (tid < ACC * 10) {
            const float2* wsrc = wchunk + (size_t)(c0 >> 1) * (2 * ACC * 10);
            cp_async16(wbase + (unsigned)(buf * 2 * ACC * 10 + tid * 2) * 8u,
                       wsrc + tid * 2);
        }
    };

    issue_stage(0); cp_commit();
    issue_stage(1); cp_commit();

    for (int s = 0; s < NS; s++) {
        const int buf = s % 3;
        cp_wait1();            // stage s complete (only group s+1 may be outstanding)
        __syncthreads();       // single barrier per stage

        #pragma unroll
        for (int cc = 0; cc < 2; cc++) {
            u64 pr[4][3];
            #pragma unroll
            for (int r = 0; r < 4; r++) {
                unsigned a = inbase + (unsigned)((buf * 2 + cc) * 34 * 36 + (2 * ty + r) * 36 + 2 * tx) * 4u;
                u64 A = lds_u64(a);
                u64 B = lds_u64(a + 8);
                float a0, a1, b0, b1;
                upk2(A, a0, a1); upk2(B, b0, b1);
                pr[r][0] = A; pr[r][1] = pk2(a1, b0); pr[r][2] = B;
            }
            #pragma unroll
            for (int i = 0; i < ACC; i++) {
                unsigned wa = wbase + (unsigned)(buf * 2 * ACC * 10) * 8u
                            + (unsigned)(cc * ACC + i) * 80u;
                u64 w[9];
                lds_v2u64(w[0], w[1], wa);
                lds_v2u64(w[2], w[3], wa + 16);
                lds_v2u64(w[4], w[5], wa + 32);
                lds_v2u64(w[6], w[7], wa + 48);
                w[8] = lds_u64(wa + 64);
                #pragma unroll
                for (int dy = 0; dy < 2; dy++)
                    #pragma unroll
                    for (int ky = 0; ky < 3; ky++)
                        #pragma unroll
                        for (int kx = 0; kx < 3; kx++)
                            fma2(acc[i][dy], pr[dy + ky][kx], w[ky * 3 + kx]);
            }
        }
        if (s + 2 < NS) issue_stage(s + 2);
        cp_commit();           // empty group when nothing issued keeps ledger aligned
    }

    const int oy = oy0 + 2 * ty, ox = ox0 + 2 * tx;
    #pragma unroll
    for (int i = 0; i < ACC; i++)
        #pragma unroll
        for (int dy = 0; dy < 2; dy++) {
            float v0, v1;
            upk2(acc[i][dy], v0, v1);
            if (ACT == 1) { v0 = fmaxf(v0, 0.f); v1 = fmaxf(v1, 0.f); }
            else if (ACT == 2) { v0 = 1.f / (1.f + expf(-v0)); v1 = 1.f / (1.f + expf(-v1)); }
            *reinterpret_cast<float2*>(out + (((size_t)b * COUT + oc0 + i) * OH + oy + dy) * OW + ox)
                = make_float2(v0, v1);
        }
}

// ============ dual-input stride-2 conv 3->64: single-shot cp.async staging ===
// 16x16 output tile, all 3 channels staged at once, one barrier, occ 3.
__global__ __launch_bounds__(256, 3)
void conv_s2_dual(const float* __restrict__ inA,
                  const float* __restrict__ inB,
                  const float* __restrict__ wt,
                  const float* __restrict__ bias,
                  float* __restrict__ out)
{
    constexpr int IT = 34;               // 16*2+2
    __shared__ float s_in[3][34][36];    // padded rows
    __shared__ float s_w[16 * 27];       // [oc][cin*9]

    const int b   = blockIdx.z >> 2;
    const int oc0 = (blockIdx.z & 3) * 16;
    const float* in = (b < BATCH) ? inA + (size_t)b * 3 * 128 * 128
                                  : inB + (size_t)(b - BATCH) * 3 * 128 * 128;
    const int tid = threadIdx.x;
    const int tx = tid & 15, ty = tid >> 4;
    const int ox = blockIdx.x * 16 + tx;
    const int oy = blockIdx.y * 16 + ty;
    const int iy0 = blockIdx.y * 32;
    const int ix0 = blockIdx.x * 32;

    const unsigned inbase = sptr(&s_in[0][0][0]);
    const int sr0 = tid >> 3;            // rows 0..31 (+32 pass 1)
    const int sc0 = tid & 7;

    // stage 3 channels of 34x34 (SAME stride-2: pad_lo=0, only high-edge bounds)
    #pragma unroll
    for (int cc = 0; cc < 3; cc++) {
        const float* ip = in + (size_t)cc * 128 * 128;
        unsigned sb = inbase + (unsigned)(cc * 34 * 36) * 4u;
        #pragma unroll
        for (int rp = 0; rp < 2; rp++) {
            int r = sr0 + rp * 32;
            if (rp == 0 || r < IT) {
                int iy = iy0 + r;
                bool rowok = (iy < 128);
                const float* iprow = ip + iy * 128;
                unsigned srow = sb + (unsigned)(r * 36) * 4u;
                #pragma unroll
                for (int j = 0; j < 5; j++) {
                    int c = sc0 + 8 * j;
                    if (j < 4 || c < IT) {
                        int ix = ix0 + c;
                        bool ok = rowok && (ix < 128);
                        const float* ga = ok ? (iprow + ix) : ip;
                        cp_async4(srow + (unsigned)c * 4u, ga, ok);
                    }
                }
            }
        }
    }
    // stage weights [oc][cin*9] — 432 elements > 256 threads: strided loop (R12 bug fix)
    #pragma unroll
    for (int idx = tid; idx < 16 * 27; idx += 256) {
        int oc = idx / 27, k27 = idx % 27;
        int cin = k27 / 9, k = k27 % 9;
        cp_async4(sptr(&s_w[oc * 27 + k27]),
                  &wt[((size_t)(oc0 + oc) * 3 + cin) * 9 + k], true);
    }
    cp_commit();
    cp_wait0();
    __syncthreads();

    float acc[16];
    #pragma unroll
    for (int i = 0; i < 16; i++) acc[i] = bias[oc0 + i];

    #pragma unroll
    for (int cc = 0; cc < 3; cc++) {
        float p[3][3];
        #pragma unroll
        for (int ky = 0; ky < 3; ky++)
            #pragma unroll
            for (int kx = 0; kx < 3; kx++)
                p[ky][kx] = s_in[cc][ty * 2 + ky][tx * 2 + kx];
        #pragma unroll
        for (int ky = 0; ky < 3; ky++)
            #pragma unroll
            for (int kx = 0; kx < 3; kx++) {
                float v = p[ky][kx];
                #pragma unroll
                for (int i = 0; i < 16; i++)
                    acc[i] = fmaf(v, s_w[i * 27 + cc * 9 + ky * 3 + kx], acc[i]);
            }
    }

    #pragma unroll
    for (int i = 0; i < 16; i++)
        out[(((size_t)b * 64 + oc0 + i) * 64 + oy) * 64 + ox] = fmaxf(acc[i], 0.f);
}

// ============ parity-combined weights for upsample conv (d_w2) ============
__global__ void wc_precompute_kernel(const float* __restrict__ w2, float2* __restrict__ wc2)
{
    int t = blockIdx.x * 256 + threadIdx.x;
    if (t >= 32 * 64) return;
    int oc = t / 64, cin = t % 64;
    int grp = oc >> 4, i = oc & 15;
    float w[3][3];
    #pragma unroll
    for (int r = 0; r < 3; r++)
        #pragma unroll
        for (int c = 0; c < 3; c++)
            w[r][c] = w2[t * 9 + r * 3 + c];
    float ry[2][2][3];
    #pragma unroll
    for (int c = 0; c < 3; c++) {
        ry[0][0][c] = w[0][c];
        ry[0][1][c] = w[1][c] + w[2][c];
        ry[1][0][c] = w[0][c] + w[1][c];
        ry[1][1][c] = w[2][c];
    }
    float2* dst = wc2 + ((size_t)(grp * 64 + cin) * 16 + i) * 8;
    #pragma unroll
    for (int py = 0; py < 2; py++)
        #pragma unroll
        for (int dr = 0; dr < 2; dr++)
            #pragma unroll
            for (int dc = 0; dc < 2; dc++) {
                float v_px0 = (dc == 0) ? ry[py][dr][0] : (ry[py][dr][1] + ry[py][dr][2]);
                float v_px1 = (dc == 0) ? (ry[py][dr][0] + ry[py][dr][1]) : ry[py][dr][2];
                dst[py * 4 + dr * 2 + dc] = make_float2(v_px0, v_px1);
            }
}

// ============ pipelined parity conv: triple-buffered, one barrier/stage ======
__global__ __launch_bounds__(256, 2)
void parity_conv_kernel(const float* __restrict__ in,
                        const float2* __restrict__ wc2,
                        const float* __restrict__ bias,
                        float* __restrict__ out)
{
    __shared__ float s_in[3][18][20];
    __shared__ __align__(16) float2 s_w[3][128];

    const int b   = blockIdx.z >> 1;
    const int grp = blockIdx.z & 1;
    const int oc0 = grp * 16;
    const int tid = threadIdx.x;
    const int tx = tid & 15, ty = tid >> 4;
    const int i0 = blockIdx.y * 16, j0 = blockIdx.x * 16;

    const int sr0 = tid >> 4;
    const int scp = tid & 15;

    u64 acc[16][2];
    #pragma unroll
    for (int i = 0; i < 16; i++) {
        float bv = bias[oc0 + i];
        acc[i][0] = pk2(bv, bv);
        acc[i][1] = acc[i][0];
    }
    const unsigned inbase = sptr(&s_in[0][0][0]);
    const unsigned wbase = sptr(&s_w[0][0]);
    const float* ipbase = in + (size_t)b * 64 * 4096;
    const float2* wgrp = wc2 + (size_t)grp * 64 * 128;

    auto issue_stage = [&](int cin) {
        const int buf = cin % 3;
        const float* ip = ipbase + (size_t)cin * 4096;
        unsigned sb = inbase + (unsigned)(buf * 18 * 20) * 4u;
        #pragma unroll
        for (int rp = 0; rp < 2; rp++) {
            int r = sr0 + rp * 16;
            if (rp == 0 || r < 18) {
                int iy = i0 - 1 + r;
                bool rowok = (iy >= 0) && (iy < 64);
                const float* iprow = ip + iy * 64;
                unsigned srow = sb + (unsigned)(r * 20) * 4u;
                #pragma unroll
                for (int j = 0; j < 2; j++) {
                    int c = scp + 16 * j;
                    if (j == 0 || c < 18) {
                        int ix = j0 - 1 + c;
                        bool ok = rowok && (ix >= 0) && (ix < 64);
                        const float* ga = ok ? (iprow + ix) : ip;
                        cp_async4(srow + (unsigned)c * 4u, ga, ok);
                    }
                }
            }
        }
        if (tid < 64)
            cp_async16(wbase + (unsigned)(buf * 128 + tid * 2) * 8u,
                       wgrp + (size_t)cin * 128 + tid * 2);
    };

    issue_stage(0); cp_commit();
    issue_stage(1); cp_commit();

    for (int cin = 0; cin < 64; ++cin) {
        const int buf = cin % 3;
        cp_wait1();
        __syncthreads();

        float p[3][3];
        #pragma unroll
        for (int r = 0; r < 3; r++)
            #pragma unroll
            for (int c = 0; c < 3; c++)
                p[r][c] = s_in[buf][ty + r][tx + c];
        u64 q[3][2];
        #pragma unroll
        for (int r = 0; r < 3; r++) {
            q[r][0] = pk2(p[r][0], p[r][1]);
            q[r][1] = pk2(p[r][1], p[r][2]);
        }

        #pragma unroll
        for (int i = 0; i < 16; i++) {
            unsigned wa = wbase + (unsigned)(buf * 128) * 8u + i * 64u;
            u64 w[8];
            lds_v2u64(w[0], w[1], wa);
            lds_v2u64(w[2], w[3], wa + 16);
            lds_v2u64(w[4], w[5], wa + 32);
            lds_v2u64(w[6], w[7], wa + 48);
            #pragma unroll
            for (int py = 0; py < 2; py++)
                #pragma unroll
                for (int dr = 0; dr < 2; dr++)
                    #pragma unroll
                    for (int dc = 0; dc < 2; dc++)
                        fma2(acc[i][py], q[py + dr][dc], w[py * 4 + dr * 2 + dc]);
        }
        if (cin + 2 < 64) issue_stage(cin + 2);
        cp_commit();
    }

    const int oy2 = 2 * (i0 + ty), ox2 = 2 * (j0 + tx);
    #pragma unroll
    for (int i = 0; i < 16; i++)
        #pragma unroll
        for (int py = 0; py < 2; py++) {
            float v0, v1;
            upk2(acc[i][py], v0, v1);
            v0 = fmaxf(v0, 0.f); v1 = fmaxf(v1, 0.f);
            *reinterpret_cast<float2*>(out + (((size_t)b * 32 + oc0 + i) * 128 + oy2 + py) * 128 + ox2)
                = make_float2(v0, v1);
        }
}

// ------- fused spatial softmax + soft-argmax moments (both streams) -------
__global__ void softmax_mu_kernel(float* __restrict__ p,
                                  float* __restrict__ mu, float* __restrict__ Li,
                                  float* __restrict__ mua, float* __restrict__ Lia)
{
    float* base = p + (size_t)blockIdx.x * 4096;
    __shared__ float red[256];
    int tid = threadIdx.x;
    float m = -1e30f;
    float vals[16];
    #pragma unroll
    for (int j = 0; j < 16; j++) { vals[j] = base[tid + j * 256]; m = fmaxf(m, vals[j]); }
    red[tid] = m; __syncthreads();
    for (int s = 128; s > 0; s >>= 1) { if (tid < s) red[tid] = fmaxf(red[tid], red[tid + s]); __syncthreads(); }
    m = red[0]; __syncthreads();
    float sum = 0.f;
    #pragma unroll
    for (int j = 0; j < 16; j++) { vals[j] = expf(vals[j] - m); sum += vals[j]; }
    float tot = block_sum256(sum, red);
    float inv = 1.f / tot;
    float s0=0,s1=0,s2=0,s3=0,s4=0;
    #pragma unroll
    for (int j = 0; j < 16; j++) {
        int i = tid + j * 256;
        float pv = vals[j] * inv;
        base[i] = pv;
        int h = i >> 6, w = i & 63;
        float gy = -1.f + 2.f * h / 63.f;
        float gx = -1.f + 2.f * w / 63.f;
        s0 += pv * gy; s1 += pv * gx;
        s2 += pv * gy * gy; s3 += pv * gy * gx; s4 += pv * gx * gx;
    }
    s0 = block_sum256(s0, red);
    s1 = block_sum256(s1, red);
    s2 = block_sum256(s2, red);
    s3 = block_sum256(s3, red);
    s4 = block_sum256(s4, red);
    if (tid == 0) {
        float muy = s0, mux = s1;
        float c00 = s2 - muy * muy, c01 = s3 - muy * mux, c11 = s4 - mux * mux;
        float a  = sqrtf(c00 + EPSV);
        float bb = c01 / (a + EPSV);
        float c  = sqrtf(fmaxf(c11 - bb * bb, 0.f) + EPSV);
        float det = a * c;
        float sc = SCALV / (det + EPSV);
        int bk = blockIdx.x;
        float* pmu = (bk < 512) ? mu : mua;
        float* pLi = (bk < 512) ? Li : Lia;
        int o = bk & 511;
        pmu[o * 2 + 0] = muy; pmu[o * 2 + 1] = mux;
        pLi[o * 4 + 0] = sc * c;     pLi[o * 4 + 1] = 0.f;
        pLi[o * 4 + 2] = sc * (-bb); pLi[o * 4 + 3] = sc * a;
    }
}

// ---------------- alpha = einsum('bfhw,bkhw->bkf') ----------------
__global__ void alpha_kernel(const float* __restrict__ fxs,
                             const float* __restrict__ parts,
                             float* __restrict__ alpha)
{
    int bk = blockIdx.x;
    int b = bk >> 4;
    __shared__ float sp[4096];
    __shared__ float red[256];
    int tid = threadIdx.x;
    const float* pb = parts + (size_t)bk * 4096;
    for (int i = tid; i < 4096; i += 256) sp[i] = pb[i];
    __syncthreads();
    for (int f = 0; f < 32; f++) {
        const float* fb = fxs + ((size_t)b * 32 + f) * 4096;
        float s = 0.f;
        for (int i = tid; i < 4096; i += 256) s += fb[i] * sp[i];
        s = block_sum256(s, red);
        if (tid == 0) alpha[(size_t)bk * 32 + f] = s;
    }
}

// ---------------- Cauchy heat render + normalization ----------------
__global__ void heat_kernel(const float* __restrict__ mu, const float* __restrict__ Linv,
                            float* __restrict__ enc, float* __restrict__ norm)
{
    int bk = blockIdx.x;
    int b = bk >> 4, k = bk & 15;
    float muy = mu[bk*2], mux = mu[bk*2+1];
    float L00 = Linv[bk*4], L01 = Linv[bk*4+1], L10 = Linv[bk*4+2], L11 = Linv[bk*4+3];
    int tid = threadIdx.x;
    __shared__ float red[256];
    float hv[16]; float sum = 0.f;
    #pragma unroll
    for (int j = 0; j < 16; j++) {
        int i = tid + j * 256;
        int h = i >> 6, w = i & 63;
        float dy = (-1.f + 2.f * h / 63.f) - muy;
        float dx = (-1.f + 2.f * w / 63.f) - mux;
        float p0 = dy * L00 + dx * L10;
        float p1 = dy * L01 + dx * L11;
        float he = 1.f / (1.f + p0 * p0 + p1 * p1);
        hv[j] = he; sum += he;
    }
    float tot = block_sum256(sum, red);
    float inv = 1.f / (tot + EPSV);
    float* eb = enc + (((size_t)b * 48 + k) * 4096);
    float* nb = norm + (size_t)bk * 4096;
    #pragma unroll
    for (int j = 0; j < 16; j++) {
        int i = tid + j * 256;
        eb[i] = hv[j];
        nb[i] = hv[j] * inv;
    }
}

// ---------------- fmap = einsum('bkf,bkhw->bfhw') -> enc ch [16,48) ----------
__global__ void fmap_kernel(const float* __restrict__ alpha,
                            const float* __restrict__ norm,
                            float* __restrict__ enc)
{
    int b = blockIdx.y;
    int pix = blockIdx.x * 256 + threadIdx.x;
    __shared__ float sal[512];
    for (int i = threadIdx.x; i < 512; i += 256) sal[i] = alpha[(size_t)b * 512 + i];
    __syncthreads();
    float nv[16];
    #pragma unroll
    for (int k = 0; k < 16; k++) nv[k] = norm[((size_t)b * 16 + k) * 4096 + pix];
    #pragma unroll
    for (int f = 0; f < 32; f++) {
        float s = 0.f;
        #pragma unroll
        for (int k = 0; k < 16; k++) s = fmaf(sal[k * 32 + f], nv[k], s);
        enc[((size_t)b * 48 + 16 + f) * 4096 + pix] = s;
    }
}

// ---------------- losses ----------------
__global__ void rec_loss_partial_kernel(const float* __restrict__ x,
                                        const float* __restrict__ rec,
                                        float* __restrict__ partial)
{
    __shared__ float red[256];
    int i0 = blockIdx.x * 1024 + threadIdx.x;
    float s = 0.f;
    #pragma unroll
    for (int j = 0; j < 4; j++) {
        int i = i0 + j * 256;
        float d = x[i] - rec[i];
        s += d * d;
    }
    s = block_sum256(s, red);
    if (threadIdx.x == 0) partial[blockIdx.x] = s;
}

__global__ void final_loss_kernel(const float* __restrict__ partial,
                                  const float* __restrict__ mu, const float* __restrict__ Li,
                                  const float* __restrict__ mua, const float* __restrict__ Lia,
                                  const float* __restrict__ coord, const float* __restrict__ vec,
                                  float* __restrict__ out, int out_size)
{
    __shared__ float red[256];
    int tid = threadIdx.x;
    float s0=0,s1=0,s2=0,s3=0;
    for (int i = tid; i < 1536; i += 256) s0 += partial[i];
    for (int i = tid; i < 1024; i += 256) { float d = mu[i] - mua[i]; s1 += d * d; }
    for (int i = tid; i < 2048; i += 256) { float d = Li[i] - Lia[i]; s2 += d * d; }
    for (int i = tid; i < 1024; i += 256) { float d = mua[i] - (coord[i] + vec[i]); s3 += d * d; }
    s0 = block_sum256(s0, red);
    s1 = block_sum256(s1, red);
    s2 = block_sum256(s2, red);
    s3 = block_sum256(s3, red);
    if (tid == 0) {
        float loss = s0 / 1572864.f + s1 / 1024.f + 0.01f * (s2 / 2048.f) + s3 / 1024.f;
        if (out_size > 1572864) out[1572864] = loss;
    }
}

// ---------------- launch ----------------
extern "C" void kernel_launch(void* const* d_in, const int* in_sizes, int n_in,
                              void* d_out, int out_size)
{
    const float* x     = (const float*)d_in[0];
    const float* xsp   = (const float*)d_in[1];
    const float* xapp  = (const float*)d_in[2];
    const float* coord = (const float*)d_in[3];
    const float* vec   = (const float*)d_in[4];
    const float* es_w1 = (const float*)d_in[5];
    const float* es_b1 = (const float*)d_in[6];
    const float* es_w2 = (const float*)d_in[7];
    const float* es_b2 = (const float*)d_in[8];
    const float* es_wp = (const float*)d_in[9];
    const float* es_bp = (const float*)d_in[10];
    const float* ea_w1 = (const float*)d_in[11];
    const float* ea_b1 = (const float*)d_in[12];
    const float* ea_w2 = (const float*)d_in[13];
    const float* ea_b2 = (const float*)d_in[14];
    const float* d_w1  = (const float*)d_in[15];
    const float* d_b1  = (const float*)d_in[16];
    const float* d_w2  = (const float*)d_in[17];
    const float* d_b2  = (const float*)d_in[18];
    const float* d_w3  = (const float*)d_in[19];
    const float* d_b3  = (const float*)d_in[20];
    float* out = (float*)d_out;

    float *h1,*h2,*t1,*parts,*normb,*fxs,*enc,*h128,*mu,*Li,*mua,*Lia,*al,*part;
    float2 *wc2, *dupw;
    cudaGetSymbolAddress((void**)&h1, g_h1);
    cudaGetSymbolAddress((void**)&h2, g_h2);
    cudaGetSymbolAddress((void**)&t1, g_t1);
    cudaGetSymbolAddress((void**)&parts, g_parts);
    cudaGetSymbolAddress((void**)&normb, g_norm);
    cudaGetSymbolAddress((void**)&fxs, g_fxs);
    cudaGetSymbolAddress((void**)&enc, g_enc);
    cudaGetSymbolAddress((void**)&h128, g_h128);
    cudaGetSymbolAddress((void**)&mu, g_mu);
    cudaGetSymbolAddress((void**)&Li, g_Linv);
    cudaGetSymbolAddress((void**)&mua, g_mua);
    cudaGetSymbolAddress((void**)&Lia, g_Linva);
    cudaGetSymbolAddress((void**)&al, g_alpha);
    cudaGetSymbolAddress((void**)&part, g_partial);
    cudaGetSymbolAddress((void**)&wc2, g_wc2);
    cudaGetSymbolAddress((void**)&dupw, g_dupw);

    const size_t IMG64 = (size_t)64 * 4096;
    const size_t PIMG  = (size_t)16 * 4096;

    dim3 blk(256);

    // Order: hot 64->64 conv is the 4th launch (ncu -s 5 -c 1 capture slot).
    dup_weights_kernel<<<(64*64*10+255)/256, blk>>>(es_w2, dupw + OFF_ESW2, 64, 64, 16);   // 1
    wc_precompute_kernel<<<8, blk>>>(d_w2, wc2);                                            // 2
    conv_s2_dual<<<dim3(4, 4, 256), blk>>>(xapp, xsp, es_w1, es_b1, h1);                    // 3
    conv3x3_f2<64,64,16,1><<<dim3(2, 2, 256), blk>>>(h1, dupw + OFF_ESW2, es_b2, h2, 64, 64); // 4 <- profile target
    dup_weights_kernel<<<(16*64*10+255)/256, blk>>>(es_wp, dupw + OFF_ESWP, 16, 64, 16);   // 5
    dup_weights_kernel<<<(64*64*10+255)/256, blk>>>(ea_w1, dupw + OFF_EAW1, 64, 64, 16);   // 6
    dup_weights_kernel<<<(32*64*10+255)/256, blk>>>(ea_w2, dupw + OFF_EAW2, 32, 64, 16);
    dup_weights_kernel<<<(64*48*10+255)/256, blk>>>(d_w1,  dupw + OFF_DW1,  64, 48, 16);
    dup_weights_kernel<<<(3*32*10+255)/256,  blk>>>(d_w3,  dupw + OFF_DW3,   3, 32, 3);

    conv3x3_f2<64,16,16,0><<<dim3(2, 2, 64),  blk>>>(h2, dupw + OFF_ESWP, es_bp, parts, 64, 64);
    softmax_mu_kernel<<<1024, blk>>>(parts, mu, Li, mua, Lia);

    // ---- appearance-only tail ----
    conv3x3_f2<64,64,16,1><<<dim3(2, 2, 128), blk>>>(h2 + BATCH * IMG64, dupw + OFF_EAW1, ea_b1, t1, 64, 64);
    conv3x3_f2<64,32,16,0><<<dim3(2, 2, 64),  blk>>>(t1, dupw + OFF_EAW2, ea_b2, fxs, 64, 64);
    alpha_kernel<<<512, blk>>>(fxs, parts + BATCH * PIMG, al);

    // ---- encoding ----
    heat_kernel<<<512, blk>>>(mu, Li, enc, normb);
    fmap_kernel<<<dim3(16, BATCH), blk>>>(al, normb, enc);

    // ---- decoder ----
    conv3x3_f2<48,64,16,1><<<dim3(2, 2, 128), blk>>>(enc, dupw + OFF_DW1, d_b1, t1, 64, 64);
    parity_conv_kernel<<<dim3(4, 4, 64), blk>>>(t1, wc2, d_b2, h128);
    conv3x3_f2<32,3,3,2><<<dim3(4, 4, 32), blk>>>(h128, dupw + OFF_DW3, d_b3, out, 128, 128);

    // ---- loss ----
    rec_loss_partial_kernel<<<1536, blk>>>(x, out, part);
    final_loss_kernel<<<1, blk>>>(part, mu, Li, mua, Lia, coord, vec, out, out_size);
}